// round 13
// baseline (speedup 1.0000x reference)
#include <cuda_runtime.h>
#include <cuda_bf16.h>

// Problem constants
#define BB 4
#define LL 512
#define DD 256
#define HH 8
#define DH 32
#define QK_SCALE 0.17677669529663687f  // 1/sqrt(32)

typedef unsigned long long ull;
typedef unsigned int uint32;

// ---------------- tf32 mma helpers ----------------
__device__ __forceinline__ void mma_tf32(float* c, const uint32* a, uint32 b0, uint32 b1) {
    asm volatile(
        "mma.sync.aligned.m16n8k8.row.col.f32.tf32.tf32.f32 "
        "{%0,%1,%2,%3}, {%4,%5,%6,%7}, {%8,%9}, {%0,%1,%2,%3};"
        : "+f"(c[0]), "+f"(c[1]), "+f"(c[2]), "+f"(c[3])
        : "r"(a[0]), "r"(a[1]), "r"(a[2]), "r"(a[3]), "r"(b0), "r"(b1));
}
__device__ __forceinline__ uint32 cvt_tf32(float f) {
    uint32 u; asm("cvt.rna.tf32.f32 %0, %1;" : "=r"(u) : "f"(f)); return u;
}

// ---------------- cp.async helpers ----------------
__device__ __forceinline__ void cp_async16(uint32 s, const void* g) {
    asm volatile("cp.async.cg.shared.global [%0], [%1], 16;" :: "r"(s), "l"(g));
}
__device__ __forceinline__ void cp_commit() {
    asm volatile("cp.async.commit_group;");
}
template <int N>
__device__ __forceinline__ void cp_wait() {
    asm volatile("cp.async.wait_group %0;" :: "n"(N));
}

// ---------------- device scratch ----------------
__device__ float g_q[BB * HH * LL * DH];   // scaled q, (B,H,L,DH)
__device__ float g_k[BB * HH * LL * DH];
__device__ float g_v[BB * HH * LL * DH];
__device__ float g_ctx[BB * LL * DD];      // ctx in (B,L,D) layout
__device__ unsigned char g_idx[BB * LL * LL]; // fused mask+distance bucket index

#define PREP_BLOCKS 256

// ---------------- kernel 1: FUSED prep_idx + QKV(all-z) GEMM ----------------
// grid 384: bid<256 -> prep (4 uchar4 groups/thread); bid>=256 -> qkv tile (128 blocks)
// qkv: one CTA computes Q,K,V for its 64x64 tile; X split once per k-chunk.
// smem floats: Ah 4352 | Al 4352 | {Bh,Bl} x3 z: 8704 each = 34816 floats (139264 B)
__global__ __launch_bounds__(256) void fused_prep_qkv_kernel(
        const void* __restrict__ mask,
        const int* __restrict__ dist,
        const float* __restrict__ X,
        const float* __restrict__ Wq, const float* __restrict__ bq,
        const float* __restrict__ Wk, const float* __restrict__ bk,
        const float* __restrict__ Wv, const float* __restrict__ bv) {
    extern __shared__ float dsm[];
    const int bid = blockIdx.x;
    const int t = threadIdx.x;

    if (bid < PREP_BLOCKS) {
        // ---------------- prep path ----------------
        int* flags = (int*)dsm;
        const unsigned int* mw = (const unsigned int*)mask;
        if (t < 2) flags[t] = 0;
        __syncthreads();
        int f1 = 0, f2 = 0;
#pragma unroll 4
        for (int i = t; i < 4096; i += 256) {
            unsigned int w = mw[i];
            if (w == 0u || w == 1u) continue;
            if (w == 0x3F800000u) { f1 = 1; continue; }
            f2 = 1;
        }
        if (f1) atomicOr(&flags[0], 1);
        if (f2) atomicOr(&flags[1], 1);
        __syncthreads();
        const int kind = flags[1] ? 2 : (flags[0] ? 1 : 0);

        const int base = bid * 1024 + t;
#pragma unroll
        for (int j = 0; j < 4; j++) {
            const int i = base + j * 256;
            int4 d4 = ((const int4*)dist)[i];
            int m0, m1, m2, m3;
            if (kind == 2) {
                uchar4 m = ((const uchar4*)mask)[i];
                m0 = m.x; m1 = m.y; m2 = m.z; m3 = m.w;
            } else if (kind == 1) {
                float4 m = ((const float4*)mask)[i];
                m0 = (m.x != 0.0f); m1 = (m.y != 0.0f); m2 = (m.z != 0.0f); m3 = (m.w != 0.0f);
            } else {
                int4 m = ((const int4*)mask)[i];
                m0 = m.x; m1 = m.y; m2 = m.z; m3 = m.w;
            }
            uchar4 o;
            o.x = m0 ? 12 : (unsigned char)d4.x;
            o.y = m1 ? 12 : (unsigned char)d4.y;
            o.z = m2 ? 12 : (unsigned char)d4.z;
            o.w = m3 ? 12 : (unsigned char)d4.w;
            ((uchar4*)g_idx)[i] = o;
        }
        return;
    }

    // ---------------- qkv path: all 3 projections for one 64x64 tile ----------------
    const int qb = bid - PREP_BLOCKS;   // 0..127
    const int by = qb >> 2, bx = qb & 3;

    float* Ah = dsm;                 // [m][k] 64*68
    float* Al = dsm + 4352;

    const int w = t >> 5, lane = t & 31;
    const int lq = lane >> 2, lc = lane & 3;
    const int wm = w >> 2, wn = w & 3;
    const int rowBase = by * 64;
    const int colBase = bx * 64;

    float cc[3][2][2][4];
#pragma unroll
    for (int z = 0; z < 3; z++)
#pragma unroll
        for (int mt = 0; mt < 2; mt++)
#pragma unroll
            for (int nt = 0; nt < 2; nt++)
#pragma unroll
                for (int e = 0; e < 4; e++) cc[z][mt][nt][e] = 0.0f;

    for (int k0 = 0; k0 < DD; k0 += 64) {
        __syncthreads();
        // load + split A (X) once
        for (int i = t; i < 1024; i += 256) {
            int m = i >> 4, k4 = (i & 15) * 4;
            float4 x = *(const float4*)(X + (rowBase + m) * DD + k0 + k4);
            float h0 = __uint_as_float(cvt_tf32(x.x));
            float h1 = __uint_as_float(cvt_tf32(x.y));
            float h2 = __uint_as_float(cvt_tf32(x.z));
            float h3 = __uint_as_float(cvt_tf32(x.w));
            *(float4*)(Ah + m * 68 + k4) = make_float4(h0, h1, h2, h3);
            *(float4*)(Al + m * 68 + k4) = make_float4(
                __uint_as_float(cvt_tf32(x.x - h0)), __uint_as_float(cvt_tf32(x.y - h1)),
                __uint_as_float(cvt_tf32(x.z - h2)), __uint_as_float(cvt_tf32(x.w - h3)));
        }
        // load + split all three W's
        for (int i = t; i < 3072; i += 256) {
            int z = i >> 10, r = i & 1023;
            int k = r >> 4, n4 = (r & 15) * 4;
            const float* W = (z == 0) ? Wq : (z == 1 ? Wk : Wv);
            float* Bh = dsm + 8704 + z * 8704;
            float4 x = *(const float4*)(W + (k0 + k) * DD + colBase + n4);
            float h0 = __uint_as_float(cvt_tf32(x.x));
            float h1 = __uint_as_float(cvt_tf32(x.y));
            float h2 = __uint_as_float(cvt_tf32(x.z));
            float h3 = __uint_as_float(cvt_tf32(x.w));
            *(float4*)(Bh + k * 68 + n4) = make_float4(h0, h1, h2, h3);
            *(float4*)(Bh + 4352 + k * 68 + n4) = make_float4(
                __uint_as_float(cvt_tf32(x.x - h0)), __uint_as_float(cvt_tf32(x.y - h1)),
                __uint_as_float(cvt_tf32(x.z - h2)), __uint_as_float(cvt_tf32(x.w - h3)));
        }
        __syncthreads();
#pragma unroll
        for (int ks = 0; ks < 8; ks++) {
            uint32 ah[2][4], al[2][4];
#pragma unroll
            for (int mt = 0; mt < 2; mt++) {
                int off = (wm * 32 + mt * 16 + lq) * 68 + ks * 8 + lc;
                ah[mt][0] = __float_as_uint(Ah[off]);
                ah[mt][1] = __float_as_uint(Ah[off + 8 * 68]);
                ah[mt][2] = __float_as_uint(Ah[off + 4]);
                ah[mt][3] = __float_as_uint(Ah[off + 8 * 68 + 4]);
                al[mt][0] = __float_as_uint(Al[off]);
                al[mt][1] = __float_as_uint(Al[off + 8 * 68]);
                al[mt][2] = __float_as_uint(Al[off + 4]);
                al[mt][3] = __float_as_uint(Al[off + 8 * 68 + 4]);
            }
#pragma unroll
            for (int z = 0; z < 3; z++) {
                const float* Bh = dsm + 8704 + z * 8704;
#pragma unroll
                for (int nt = 0; nt < 2; nt++) {
                    int off = (ks * 8 + lc) * 68 + wn * 16 + nt * 8 + lq;
                    uint32 bh0 = __float_as_uint(Bh[off]);
                    uint32 bh1 = __float_as_uint(Bh[off + 4 * 68]);
                    uint32 bl0 = __float_as_uint(Bh[4352 + off]);
                    uint32 bl1 = __float_as_uint(Bh[4352 + off + 4 * 68]);
                    mma_tf32(cc[z][0][nt], ah[0], bh0, bh1);
                    mma_tf32(cc[z][0][nt], al[0], bh0, bh1);
                    mma_tf32(cc[z][0][nt], ah[0], bl0, bl1);
                    mma_tf32(cc[z][1][nt], ah[1], bh0, bh1);
                    mma_tf32(cc[z][1][nt], al[1], bh0, bh1);
                    mma_tf32(cc[z][1][nt], ah[1], bl0, bl1);
                }
            }
        }
    }

#pragma unroll
    for (int z = 0; z < 3; z++) {
        const float* bias = (z == 0) ? bq : (z == 1 ? bk : bv);
        float* out        = (z == 0) ? g_q : (z == 1 ? g_k : g_v);
        const float scale = (z == 0) ? QK_SCALE : 1.0f;
#pragma unroll
        for (int mt = 0; mt < 2; mt++) {
#pragma unroll
            for (int nt = 0; nt < 2; nt++) {
                int col0 = colBase + wn * 16 + nt * 8 + 2 * lc;
                int h = col0 >> 5, d = col0 & 31;
                float bx2 = bias[col0], by2 = bias[col0 + 1];
                int r0 = rowBase + wm * 32 + mt * 16 + lq;
                {
                    int b = r0 >> 9, l = r0 & 511;
                    float2 o = make_float2((cc[z][mt][nt][0] + bx2) * scale,
                                           (cc[z][mt][nt][1] + by2) * scale);
                    *(float2*)(out + (((b * HH + h) * LL) + l) * DH + d) = o;
                }
                {
                    int r1 = r0 + 8;
                    int b = r1 >> 9, l = r1 & 511;
                    float2 o = make_float2((cc[z][mt][nt][2] + bx2) * scale,
                                           (cc[z][mt][nt][3] + by2) * scale);
                    *(float2*)(out + (((b * HH + h) * LL) + l) * DH + d) = o;
                }
            }
        }
    }
}

// ---------------- kernel 2: fused attention, 64-row chunks, depth-2 pipeline ----------------
// smem floats: S 8256 | B0/B1/B2 3x2304 | qu 528 | Ps 256 | invp 16 | part 128 = 16096
__global__ __launch_bounds__(256, 3) void attn_kernel(
        const float* __restrict__ uvec,
        const float* __restrict__ vvec,
        const float* __restrict__ rel_table,
        float* __restrict__ attn) {
    extern __shared__ float sm[];
    float* S    = sm;                    // [16][516]
    float* B0   = sm + 8256;             // [64][36]
    float* B1   = sm + 10560;
    float* B2   = sm + 12864;
    float* qu   = sm + 15168;            // [16][33]
    float* Ps   = qu + 528;              // [16][16]
    float* invp = Ps + 256;              // [16]
    float* part = invp + 16;             // [16][8]

    const int bh = blockIdx.y;
    const int b = bh >> 3, h = bh & 7;
    const int q0 = blockIdx.x * 16;
    const int t = threadIdx.x;
    const int w = t >> 5;
    const int lane = t & 31;
    const int lq = lane >> 2;
    const int lc = lane & 3;

    const float* kbase = g_k + (size_t)bh * LL * DH;
    const float* vbase = g_v + (size_t)bh * LL * DH;
    const float* bufs[3] = {B0, B1, B2};
    const uint32 sB[3] = {
        (uint32)__cvta_generic_to_shared(B0),
        (uint32)__cvta_generic_to_shared(B1),
        (uint32)__cvta_generic_to_shared(B2)};

    // issue a 64-row chunk (2048 floats) into buffer bi
    auto issue = [&](const float* src, int bi) {
#pragma unroll
        for (int i = 0; i < 2; i++) {
            int idx = t + i * 256;
            int k = idx >> 3, seg = idx & 7;
            cp_async16(sB[bi] + k * 144 + seg * 16, src + k * 32 + seg * 4);
        }
        cp_commit();
    };

    // prologue: K0 -> B0, K1 -> B1
    issue(kbase, 0);
    issue(kbase + 2048, 1);

    // -------- phase 0: qu = q+v, table slice (in S), P --------
    if (t < 128) {
        int q = t >> 3, d4 = (t & 7) * 4;
        float4 qv = *(const float4*)(g_q + ((size_t)bh * LL + q0 + q) * DH + d4);
        float4 vv = *(const float4*)(vvec + h * DH + d4);
        qu[q * 33 + d4 + 0] = qv.x + vv.x;
        qu[q * 33 + d4 + 1] = qv.y + vv.y;
        qu[q * 33 + d4 + 2] = qv.z + vv.z;
        qu[q * 33 + d4 + 3] = qv.w + vv.w;
    }
    float* tbl = S;   // [12][33] scratch inside S (consumed before S is written)
    for (int i = t; i < 384; i += 256) {
        int bu = i >> 5, d = i & 31;
        tbl[bu * 33 + d] = rel_table[bu * DD + h * DH + d];
    }
    __syncthreads();
    if (t < 192) {
        int q = t / 12, bu = t - q * 12;
        const float* qp = qu + q * 33;
        const float* tp = tbl + bu * 33;
        float s = 0.0f;
#pragma unroll
        for (int d = 0; d < 32; d++) s = fmaf(qp[d], tp[d], s);
        Ps[q * 16 + bu] = s;
    }
    if (t < 16) Ps[t * 16 + 12] = -1e18f;
    __syncthreads();
    if (t < 128) {
        int q = t >> 3, d4 = (t & 7) * 4;
        float4 uu = *(const float4*)(uvec + h * DH + d4);
        float4 vv = *(const float4*)(vvec + h * DH + d4);
        qu[q * 33 + d4 + 0] += uu.x - vv.x;
        qu[q * 33 + d4 + 1] += uu.y - vv.y;
        qu[q * 33 + d4 + 2] += uu.z - vv.z;
        qu[q * 33 + d4 + 3] += uu.w - vv.w;
    }
    __syncthreads();

    // -------- K loop: 8 chunks of 64 rows, prefetch depth 2 --------
    float rsum0 = 0.0f, rsum1 = 0.0f;
#pragma unroll
    for (int c = 0; c < 8; c++) {
        cp_wait<1>();
        __syncthreads();
        const float* buf = bufs[c % 3];

        float cc[4] = {0.0f, 0.0f, 0.0f, 0.0f};
        const int kn = w * 8 + lq;
#pragma unroll
        for (int ks = 0; ks < 4; ks++) {
            uint32 a[4];
            int off = lq * 33 + ks * 8 + lc;
            a[0] = __float_as_uint(qu[off]);
            a[1] = __float_as_uint(qu[off + 8 * 33]);
            a[2] = __float_as_uint(qu[off + 4]);
            a[3] = __float_as_uint(qu[off + 8 * 33 + 4]);
            uint32 b0 = __float_as_uint(buf[kn * 36 + ks * 8 + lc]);
            uint32 b1 = __float_as_uint(buf[kn * 36 + ks * 8 + lc + 4]);
            mma_tf32(cc, a, b0, b1);
        }

        // epilogue: P-gather, exp, rsum, store S
        {
            int kk = c * 64 + w * 8 + 2 * lc;
            unsigned int u0 = *(const unsigned short*)
                (g_idx + ((size_t)(b * LL + q0 + lq)) * LL + kk);
            unsigned int u1 = *(const unsigned short*)
                (g_idx + ((size_t)(b * LL + q0 + lq + 8)) * LL + kk);
            const float* P0 = Ps + lq * 16;
            const float* P1 = Ps + (lq + 8) * 16;
            float e00 = __expf(cc[0] + P0[u0 & 255]);
            float e01 = __expf(cc[1] + P0[(u0 >> 8) & 255]);
            float e10 = __expf(cc[2] + P1[u1 & 255]);
            float e11 = __expf(cc[3] + P1[(u1 >> 8) & 255]);
            rsum0 += e00 + e01;
            rsum1 += e10 + e11;
            *(float2*)(S + lq * 516 + kk) = make_float2(e00, e01);
            *(float2*)(S + (lq + 8) * 516 + kk) = make_float2(e10, e11);
        }

        // issue next chunk (K_{c+2}, or V0/V1 at the tail)
        if (c < 6)      issue(kbase + (c + 2) * 2048, (c + 2) % 3);
        else if (c == 6) issue(vbase, 2);           // g8 -> buf 2
        else             issue(vbase + 2048, 0);    // g9 -> buf 0
    }

    // -------- row-sum reduction + invp --------
    rsum0 += __shfl_xor_sync(0xffffffffu, rsum0, 1);
    rsum0 += __shfl_xor_sync(0xffffffffu, rsum0, 2);
    rsum1 += __shfl_xor_sync(0xffffffffu, rsum1, 1);
    rsum1 += __shfl_xor_sync(0xffffffffu, rsum1, 2);
    if (lc == 0) {
        part[lq * 8 + w] = rsum0;
        part[(lq + 8) * 8 + w] = rsum1;
    }
    __syncthreads();
    if (t < 16) {
        const float* pr = part + t * 8;
        float s = pr[0] + pr[1] + pr[2] + pr[3] + pr[4] + pr[5] + pr[6] + pr[7];
        invp[t] = 1.0f / s;
    }
    __syncthreads();

    // -------- write normalized attn --------
    float* arow = attn + ((size_t)(bh * LL + q0)) * LL;
    for (int i = t; i < 16 * 128; i += 256) {
        int r = i >> 7, c4 = (i & 127) << 2;
        float iv = invp[r];
        float4 e = *(const float4*)(S + r * 516 + c4);
        float4 o = make_float4(e.x * iv, e.y * iv, e.z * iv, e.w * iv);
        *(float4*)(arow + r * LL + c4) = o;
    }

    // -------- V loop: ctx accumulation, 8 chunks --------
    float cv[4][4];
#pragma unroll
    for (int nt = 0; nt < 4; nt++)
#pragma unroll
        for (int e = 0; e < 4; e++) cv[nt][e] = 0.0f;

#pragma unroll
    for (int c = 0; c < 8; c++) {
        if (c < 7) cp_wait<1>(); else cp_wait<0>();
        __syncthreads();
        const float* buf = bufs[(8 + c) % 3];

        uint32 a[4];
        {
            const float* ab = S + lq * 516 + c * 64 + w * 8 + lc;
            a[0] = cvt_tf32(ab[0]);
            a[1] = cvt_tf32(ab[8 * 516]);
            a[2] = cvt_tf32(ab[4]);
            a[3] = cvt_tf32(ab[8 * 516 + 4]);
        }
#pragma unroll
        for (int nt = 0; nt < 4; nt++) {
            int dn = nt * 8 + lq;
            uint32 b0 = __float_as_uint(buf[(w * 8 + lc) * 36 + dn]);
            uint32 b1 = __float_as_uint(buf[(w * 8 + lc + 4) * 36 + dn]);
            mma_tf32(cv[nt], a, b0, b1);
        }

        if (c < 6) issue(vbase + (c + 2) * 2048, (10 + c) % 3);
    }
    __syncthreads();

    // -------- two-stage cross-warp reduction: 8 partials [16][34] in buffer region --------
    float* red = B0;
    if (w >= 4) {
        float* rg = red + (w - 4) * 544;
#pragma unroll
        for (int nt = 0; nt < 4; nt++) {
            int dc = nt * 8 + 2 * lc;
            *(float2*)(rg + lq * 34 + dc) = make_float2(cv[nt][0], cv[nt][1]);
            *(float2*)(rg + (lq + 8) * 34 + dc) = make_float2(cv[nt][2], cv[nt][3]);
        }
    }
    __syncthreads();
    if (w < 4) {
        float* rg = red + w * 544;
#pragma unroll
        for (int nt = 0; nt < 4; nt++) {
            int dc = nt * 8 + 2 * lc;
            float2 p0 = *(const float2*)(rg + lq * 34 + dc);
            float2 p1 = *(const float2*)(rg + (lq + 8) * 34 + dc);
            *(float2*)(rg + lq * 34 + dc) =
                make_float2(cv[nt][0] + p0.x, cv[nt][1] + p0.y);
            *(float2*)(rg + (lq + 8) * 34 + dc) =
                make_float2(cv[nt][2] + p1.x, cv[nt][3] + p1.y);
        }
    }
    __syncthreads();
    if (t < 128) {
        int q = t >> 3, d4 = (t & 7) * 4;
        float iv = invp[q];
        float o[4];
#pragma unroll
        for (int j = 0; j < 4; j++) {
            int off = q * 34 + d4 + j;
            o[j] = red[off] + red[544 + off] + red[1088 + off] + red[1632 + off];
        }
        float4 ov = make_float4(o[0] * iv, o[1] * iv, o[2] * iv, o[3] * iv);
        *(float4*)(g_ctx + ((size_t)(b * LL) + q0 + q) * DD + h * DH + d4) = ov;
    }
}

// ---------------- kernel 3: output GEMM (tf32 3-MMA, 64x64 tiles, hoisted split) ----------------
__global__ __launch_bounds__(256) void out_gemm_kernel(
        const float* __restrict__ Wo,
        const float* __restrict__ bo,
        float* __restrict__ out) {
    extern __shared__ float dsm[];
    float* Ah = dsm;
    float* Al = dsm + 4352;
    float* Bh = dsm + 8704;
    float* Bl = dsm + 13056;

    const int t = threadIdx.x;
    const int w = t >> 5, lane = t & 31;
    const int lq = lane >> 2, lc = lane & 3;
    const int wm = w >> 2, wn = w & 3;
    const int rowBase = blockIdx.y * 64;
    const int colBase = blockIdx.x * 64;

    float cc[2][2][4];
#pragma unroll
    for (int mt = 0; mt < 2; mt++)
#pragma unroll
        for (int nt = 0; nt < 2; nt++)
#pragma unroll
            for (int e = 0; e < 4; e++) cc[mt][nt][e] = 0.0f;

    for (int k0 = 0; k0 < DD; k0 += 64) {
        for (int i = t; i < 1024; i += 256) {
            int m = i >> 4, k4 = (i & 15) * 4;
            float4 x = *(const float4*)(g_ctx + (rowBase + m) * DD + k0 + k4);
            float h0 = __uint_as_float(cvt_tf32(x.x));
            float h1 = __uint_as_float(cvt_tf32(x.y));
            float h2 = __uint_as_float(cvt_tf32(x.z));
            float h3 = __uint_as_float(cvt_tf32(x.w));
            *(float4*)(Ah + m * 68 + k4) = make_float4(h0, h1, h2, h3);
            *(float4*)(Al + m * 68 + k4) = make_float4(
                __uint_as_float(cvt_tf32(x.x - h0)), __uint_as_float(cvt_tf32(x.y - h1)),
                __uint_as_float(cvt_tf32(x.z - h2)), __uint_as_float(cvt_tf32(x.w - h3)));
        }
        for (int i = t; i < 1024; i += 256) {
            int k = i >> 4, n4 = (i & 15) * 4;
            float4 x = *(const float4*)(Wo + (k0 + k) * DD + colBase + n4);
            float h0 = __uint_as_float(cvt_tf32(x.x));
            float h1 = __uint_as_float(cvt_tf32(x.y));
            float h2 = __uint_as_float(cvt_tf32(x.z));
            float h3 = __uint_as_float(cvt_tf32(x.w));
            *(float4*)(Bh + k * 68 + n4) = make_float4(h0, h1, h2, h3);
            *(float4*)(Bl + k * 68 + n4) = make_float4(
                __uint_as_float(cvt_tf32(x.x - h0)), __uint_as_float(cvt_tf32(x.y - h1)),
                __uint_as_float(cvt_tf32(x.z - h2)), __uint_as_float(cvt_tf32(x.w - h3)));
        }
        __syncthreads();
#pragma unroll
        for (int ks = 0; ks < 8; ks++) {
            uint32 ah[2][4], al[2][4];
#pragma unroll
            for (int mt = 0; mt < 2; mt++) {
                int off = (wm * 32 + mt * 16 + lq) * 68 + ks * 8 + lc;
                ah[mt][0] = __float_as_uint(Ah[off]);
                ah[mt][1] = __float_as_uint(Ah[off + 8 * 68]);
                ah[mt][2] = __float_as_uint(Ah[off + 4]);
                ah[mt][3] = __float_as_uint(Ah[off + 8 * 68 + 4]);
                al[mt][0] = __float_as_uint(Al[off]);
                al[mt][1] = __float_as_uint(Al[off + 8 * 68]);
                al[mt][2] = __float_as_uint(Al[off + 4]);
                al[mt][3] = __float_as_uint(Al[off + 8 * 68 + 4]);
            }
#pragma unroll
            for (int nt = 0; nt < 2; nt++) {
                int off = (ks * 8 + lc) * 68 + wn * 16 + nt * 8 + lq;
                uint32 bh0 = __float_as_uint(Bh[off]);
                uint32 bh1 = __float_as_uint(Bh[off + 4 * 68]);
                uint32 bl0 = __float_as_uint(Bl[off]);
                uint32 bl1 = __float_as_uint(Bl[off + 4 * 68]);
                mma_tf32(cc[0][nt], ah[0], bh0, bh1);
                mma_tf32(cc[0][nt], al[0], bh0, bh1);
                mma_tf32(cc[0][nt], ah[0], bl0, bl1);
                mma_tf32(cc[1][nt], ah[1], bh0, bh1);
                mma_tf32(cc[1][nt], al[1], bh0, bh1);
                mma_tf32(cc[1][nt], ah[1], bl0, bl1);
            }
        }
        __syncthreads();
    }

#pragma unroll
    for (int mt = 0; mt < 2; mt++) {
#pragma unroll
        for (int nt = 0; nt < 2; nt++) {
            int col0 = colBase + wn * 16 + nt * 8 + 2 * lc;
            float bx = bo[col0], by = bo[col0 + 1];
            int r0 = rowBase + wm * 32 + mt * 16 + lq;
            *(float2*)(out + r0 * DD + col0) =
                make_float2(cc[mt][nt][0] + bx, cc[mt][nt][1] + by);
            *(float2*)(out + (r0 + 8) * DD + col0) =
                make_float2(cc[mt][nt][2] + bx, cc[mt][nt][3] + by);
        }
    }
}

// ---------------- launch ----------------
extern "C" void kernel_launch(void* const* d_in, const int* in_sizes, int n_in,
                              void* d_out, int out_size) {
    const float* X         = (const float*)d_in[0];
    const void*  mask      = d_in[1];
    const int*   distances = (const int*)d_in[2];
    const float* Wq        = (const float*)d_in[3];
    const float* bq        = (const float*)d_in[4];
    const float* Wk        = (const float*)d_in[5];
    const float* bk        = (const float*)d_in[6];
    const float* Wv        = (const float*)d_in[7];
    const float* bv        = (const float*)d_in[8];
    const float* Wo        = (const float*)d_in[9];
    const float* bo        = (const float*)d_in[10];
    const float* rel_table = (const float*)d_in[11];
    const float* uvec      = (const float*)d_in[12];
    const float* vvec      = (const float*)d_in[13];

    float* out  = (float*)d_out;                       // (B,L,D)
    float* attn = (float*)d_out + BB * LL * DD;        // (B,H,L,L)

    const int qkv_smem  = 34816 * 4;      // 139264 B
    const int attn_smem = 16096 * 4;      // 64384 B
    const int out_smem  = 17408 * 4;      // 69632 B
    static int smem_set = 0;
    if (!smem_set) {
        cudaFuncSetAttribute(fused_prep_qkv_kernel,
                             cudaFuncAttributeMaxDynamicSharedMemorySize, qkv_smem);
        cudaFuncSetAttribute(attn_kernel,
                             cudaFuncAttributeMaxDynamicSharedMemorySize, attn_smem);
        cudaFuncSetAttribute(out_gemm_kernel,
                             cudaFuncAttributeMaxDynamicSharedMemorySize, out_smem);
        smem_set = 1;
    }

    fused_prep_qkv_kernel<<<PREP_BLOCKS + 128, 256, qkv_smem>>>(
        mask, distances, X, Wq, bq, Wk, bk, Wv, bv);
    attn_kernel<<<dim3(32, 32), 256, attn_smem>>>(uvec, vvec, rel_table, attn);
    out_gemm_kernel<<<dim3(4, 32), 256, out_smem>>>(Wo, bo, out);
}

// round 14
// speedup vs baseline: 1.0648x; 1.0648x over previous
#include <cuda_runtime.h>
#include <cuda_bf16.h>

// Problem constants
#define BB 4
#define LL 512
#define DD 256
#define HH 8
#define DH 32
#define QK_SCALE 0.17677669529663687f  // 1/sqrt(32)

typedef unsigned long long ull;
typedef unsigned int uint32;

// ---------------- tf32 mma helpers ----------------
__device__ __forceinline__ void mma_tf32(float* c, const uint32* a, uint32 b0, uint32 b1) {
    asm volatile(
        "mma.sync.aligned.m16n8k8.row.col.f32.tf32.tf32.f32 "
        "{%0,%1,%2,%3}, {%4,%5,%6,%7}, {%8,%9}, {%0,%1,%2,%3};"
        : "+f"(c[0]), "+f"(c[1]), "+f"(c[2]), "+f"(c[3])
        : "r"(a[0]), "r"(a[1]), "r"(a[2]), "r"(a[3]), "r"(b0), "r"(b1));
}
__device__ __forceinline__ uint32 cvt_tf32(float f) {
    uint32 u; asm("cvt.rna.tf32.f32 %0, %1;" : "=r"(u) : "f"(f)); return u;
}

// ---------------- cp.async helpers ----------------
__device__ __forceinline__ void cp_async16(uint32 s, const void* g) {
    asm volatile("cp.async.cg.shared.global [%0], [%1], 16;" :: "r"(s), "l"(g));
}
__device__ __forceinline__ void cp_commit() {
    asm volatile("cp.async.commit_group;");
}
template <int N>
__device__ __forceinline__ void cp_wait() {
    asm volatile("cp.async.wait_group %0;" :: "n"(N));
}

// ---------------- device scratch ----------------
__device__ float g_q[BB * HH * LL * DH];   // scaled q, (B,H,L,DH)
__device__ float g_k[BB * HH * LL * DH];
__device__ float g_v[BB * HH * LL * DH];
__device__ float g_ctx[BB * LL * DD];      // ctx in (B,L,D) layout
__device__ unsigned char g_idx[BB * LL * LL]; // fused mask+distance bucket index

// ---------------- kernel 1: FUSED prep_idx + QKV GEMM (R12 version) ----------------
// grid 1408 blocks: bid<384 -> qkv (z=bid/128, by=(bid%128)>>2, bx=bid&3)
//                   bid>=384 -> prep block (1024 blocks)
__global__ __launch_bounds__(256) void fused_prep_qkv_kernel(
        const void* __restrict__ mask,
        const int* __restrict__ dist,
        const float* __restrict__ X,
        const float* __restrict__ Wq, const float* __restrict__ bq,
        const float* __restrict__ Wk, const float* __restrict__ bk,
        const float* __restrict__ Wv, const float* __restrict__ bv) {
    extern __shared__ float dsm[];
    const int bid = blockIdx.x;
    const int t = threadIdx.x;

    if (bid >= 384) {
        // ---------------- prep path ----------------
        int* flags = (int*)dsm;
        const unsigned int* mw = (const unsigned int*)mask;
        if (t < 2) flags[t] = 0;
        __syncthreads();
        int f1 = 0, f2 = 0;
#pragma unroll 4
        for (int i = t; i < 4096; i += 256) {
            unsigned int w = mw[i];
            if (w == 0u || w == 1u) continue;
            if (w == 0x3F800000u) { f1 = 1; continue; }
            f2 = 1;
        }
        if (f1) atomicOr(&flags[0], 1);
        if (f2) atomicOr(&flags[1], 1);
        __syncthreads();
        const int kind = flags[1] ? 2 : (flags[0] ? 1 : 0);

        const int i = (bid - 384) * 256 + t;
        int4 d4 = ((const int4*)dist)[i];
        int m0, m1, m2, m3;
        if (kind == 2) {
            uchar4 m = ((const uchar4*)mask)[i];
            m0 = m.x; m1 = m.y; m2 = m.z; m3 = m.w;
        } else if (kind == 1) {
            float4 m = ((const float4*)mask)[i];
            m0 = (m.x != 0.0f); m1 = (m.y != 0.0f); m2 = (m.z != 0.0f); m3 = (m.w != 0.0f);
        } else {
            int4 m = ((const int4*)mask)[i];
            m0 = m.x; m1 = m.y; m2 = m.z; m3 = m.w;
        }
        uchar4 o;
        o.x = m0 ? 12 : (unsigned char)d4.x;
        o.y = m1 ? 12 : (unsigned char)d4.y;
        o.z = m2 ? 12 : (unsigned char)d4.z;
        o.w = m3 ? 12 : (unsigned char)d4.w;
        ((uchar4*)g_idx)[i] = o;
        return;
    }

    // ---------------- qkv path ----------------
    const int z = bid >> 7;
    const int rem = bid & 127;
    const int by = rem >> 2;
    const int bx = rem & 3;

    const float* W    = (z == 0) ? Wq : (z == 1 ? Wk : Wv);
    const float* bias = (z == 0) ? bq : (z == 1 ? bk : bv);
    float* out        = (z == 0) ? g_q : (z == 1 ? g_k : g_v);
    const float scale = (z == 0) ? QK_SCALE : 1.0f;

    float* Ah = dsm;                 // [m][k] 64*68
    float* Al = dsm + 4352;
    float* Bh = dsm + 8704;          // [k][n] 64*68
    float* Bl = dsm + 13056;

    const int w = t >> 5, lane = t & 31;
    const int lq = lane >> 2, lc = lane & 3;
    const int wm = w >> 2, wn = w & 3;
    const int rowBase = by * 64;
    const int colBase = bx * 64;

    float cc[2][2][4];
#pragma unroll
    for (int mt = 0; mt < 2; mt++)
#pragma unroll
        for (int nt = 0; nt < 2; nt++)
#pragma unroll
            for (int e = 0; e < 4; e++) cc[mt][nt][e] = 0.0f;

    for (int k0 = 0; k0 < DD; k0 += 64) {
        for (int i = t; i < 1024; i += 256) {
            int m = i >> 4, k4 = (i & 15) * 4;
            float4 x = *(const float4*)(X + (rowBase + m) * DD + k0 + k4);
            float h0 = __uint_as_float(cvt_tf32(x.x));
            float h1 = __uint_as_float(cvt_tf32(x.y));
            float h2 = __uint_as_float(cvt_tf32(x.z));
            float h3 = __uint_as_float(cvt_tf32(x.w));
            *(float4*)(Ah + m * 68 + k4) = make_float4(h0, h1, h2, h3);
            *(float4*)(Al + m * 68 + k4) = make_float4(
                __uint_as_float(cvt_tf32(x.x - h0)), __uint_as_float(cvt_tf32(x.y - h1)),
                __uint_as_float(cvt_tf32(x.z - h2)), __uint_as_float(cvt_tf32(x.w - h3)));
        }
        for (int i = t; i < 1024; i += 256) {
            int k = i >> 4, n4 = (i & 15) * 4;
            float4 x = *(const float4*)(W + (k0 + k) * DD + colBase + n4);
            float h0 = __uint_as_float(cvt_tf32(x.x));
            float h1 = __uint_as_float(cvt_tf32(x.y));
            float h2 = __uint_as_float(cvt_tf32(x.z));
            float h3 = __uint_as_float(cvt_tf32(x.w));
            *(float4*)(Bh + k * 68 + n4) = make_float4(h0, h1, h2, h3);
            *(float4*)(Bl + k * 68 + n4) = make_float4(
                __uint_as_float(cvt_tf32(x.x - h0)), __uint_as_float(cvt_tf32(x.y - h1)),
                __uint_as_float(cvt_tf32(x.z - h2)), __uint_as_float(cvt_tf32(x.w - h3)));
        }
        __syncthreads();
#pragma unroll
        for (int ks = 0; ks < 8; ks++) {
            uint32 ah[2][4], al[2][4];
#pragma unroll
            for (int mt = 0; mt < 2; mt++) {
                int off = (wm * 32 + mt * 16 + lq) * 68 + ks * 8 + lc;
                ah[mt][0] = __float_as_uint(Ah[off]);
                ah[mt][1] = __float_as_uint(Ah[off + 8 * 68]);
                ah[mt][2] = __float_as_uint(Ah[off + 4]);
                ah[mt][3] = __float_as_uint(Ah[off + 8 * 68 + 4]);
                al[mt][0] = __float_as_uint(Al[off]);
                al[mt][1] = __float_as_uint(Al[off + 8 * 68]);
                al[mt][2] = __float_as_uint(Al[off + 4]);
                al[mt][3] = __float_as_uint(Al[off + 8 * 68 + 4]);
            }
#pragma unroll
            for (int nt = 0; nt < 2; nt++) {
                int off = (ks * 8 + lc) * 68 + wn * 16 + nt * 8 + lq;
                uint32 bh0 = __float_as_uint(Bh[off]);
                uint32 bh1 = __float_as_uint(Bh[off + 4 * 68]);
                uint32 bl0 = __float_as_uint(Bl[off]);
                uint32 bl1 = __float_as_uint(Bl[off + 4 * 68]);
                mma_tf32(cc[0][nt], ah[0], bh0, bh1);
                mma_tf32(cc[0][nt], al[0], bh0, bh1);
                mma_tf32(cc[0][nt], ah[0], bl0, bl1);
                mma_tf32(cc[1][nt], ah[1], bh0, bh1);
                mma_tf32(cc[1][nt], al[1], bh0, bh1);
                mma_tf32(cc[1][nt], ah[1], bl0, bl1);
            }
        }
        __syncthreads();
    }

#pragma unroll
    for (int mt = 0; mt < 2; mt++) {
#pragma unroll
        for (int nt = 0; nt < 2; nt++) {
            int col0 = colBase + wn * 16 + nt * 8 + 2 * lc;
            int h = col0 >> 5, d = col0 & 31;
            float bx2 = bias[col0], by2 = bias[col0 + 1];
            int r0 = rowBase + wm * 32 + mt * 16 + lq;
            {
                int b = r0 >> 9, l = r0 & 511;
                float2 o = make_float2((cc[mt][nt][0] + bx2) * scale,
                                       (cc[mt][nt][1] + by2) * scale);
                *(float2*)(out + (((b * HH + h) * LL) + l) * DH + d) = o;
            }
            {
                int r1 = r0 + 8;
                int b = r1 >> 9, l = r1 & 511;
                float2 o = make_float2((cc[mt][nt][2] + bx2) * scale,
                                       (cc[mt][nt][3] + by2) * scale);
                *(float2*)(out + (((b * HH + h) * LL) + l) * DH + d) = o;
            }
        }
    }
}

// ---------------- kernel 2: fused attention, 64-row chunks, depth-2 pipeline ----------------
// smem floats: S 8256 | B0/B1/B2 3x2304 | qu 528 | Ps 256 | invp 16 | part 128 = 16096
__global__ __launch_bounds__(256, 3) void attn_kernel(
        const float* __restrict__ uvec,
        const float* __restrict__ vvec,
        const float* __restrict__ rel_table,
        float* __restrict__ attn) {
    extern __shared__ float sm[];
    float* S    = sm;                    // [16][516]
    float* B0   = sm + 8256;             // [64][36]
    float* B1   = sm + 10560;
    float* B2   = sm + 12864;
    float* qu   = sm + 15168;            // [16][33]
    float* Ps   = qu + 528;              // [16][16]
    float* invp = Ps + 256;              // [16]
    float* part = invp + 16;             // [16][8]

    const int bh = blockIdx.y;
    const int b = bh >> 3, h = bh & 7;
    const int q0 = blockIdx.x * 16;
    const int t = threadIdx.x;
    const int w = t >> 5;
    const int lane = t & 31;
    const int lq = lane >> 2;
    const int lc = lane & 3;

    const float* kbase = g_k + (size_t)bh * LL * DH;
    const float* vbase = g_v + (size_t)bh * LL * DH;
    const float* bufs[3] = {B0, B1, B2};
    const uint32 sB[3] = {
        (uint32)__cvta_generic_to_shared(B0),
        (uint32)__cvta_generic_to_shared(B1),
        (uint32)__cvta_generic_to_shared(B2)};

    auto issue = [&](const float* src, int bi) {
#pragma unroll
        for (int i = 0; i < 2; i++) {
            int idx = t + i * 256;
            int k = idx >> 3, seg = idx & 7;
            cp_async16(sB[bi] + k * 144 + seg * 16, src + k * 32 + seg * 4);
        }
        cp_commit();
    };

    // prologue: K0 -> B0, K1 -> B1
    issue(kbase, 0);
    issue(kbase + 2048, 1);

    // -------- phase 0: qu = q+v, table slice (in S), P --------
    if (t < 128) {
        int q = t >> 3, d4 = (t & 7) * 4;
        float4 qv = *(const float4*)(g_q + ((size_t)bh * LL + q0 + q) * DH + d4);
        float4 vv = *(const float4*)(vvec + h * DH + d4);
        qu[q * 33 + d4 + 0] = qv.x + vv.x;
        qu[q * 33 + d4 + 1] = qv.y + vv.y;
        qu[q * 33 + d4 + 2] = qv.z + vv.z;
        qu[q * 33 + d4 + 3] = qv.w + vv.w;
    }
    float* tbl = S;   // [12][33] scratch inside S (consumed before S is written)
    for (int i = t; i < 384; i += 256) {
        int bu = i >> 5, d = i & 31;
        tbl[bu * 33 + d] = rel_table[bu * DD + h * DH + d];
    }
    __syncthreads();
    if (t < 192) {
        int q = t / 12, bu = t - q * 12;
        const float* qp = qu + q * 33;
        const float* tp = tbl + bu * 33;
        float s = 0.0f;
#pragma unroll
        for (int d = 0; d < 32; d++) s = fmaf(qp[d], tp[d], s);
        Ps[q * 16 + bu] = s;
    }
    if (t < 16) Ps[t * 16 + 12] = -1e18f;
    __syncthreads();
    if (t < 128) {
        int q = t >> 3, d4 = (t & 7) * 4;
        float4 uu = *(const float4*)(uvec + h * DH + d4);
        float4 vv = *(const float4*)(vvec + h * DH + d4);
        qu[q * 33 + d4 + 0] += uu.x - vv.x;
        qu[q * 33 + d4 + 1] += uu.y - vv.y;
        qu[q * 33 + d4 + 2] += uu.z - vv.z;
        qu[q * 33 + d4 + 3] += uu.w - vv.w;
    }
    __syncthreads();

    // -------- K loop: 8 chunks of 64 rows, prefetch depth 2 --------
    float rsum0 = 0.0f, rsum1 = 0.0f;
#pragma unroll
    for (int c = 0; c < 8; c++) {
        cp_wait<1>();
        __syncthreads();
        const float* buf = bufs[c % 3];

        float cc[4] = {0.0f, 0.0f, 0.0f, 0.0f};
        const int kn = w * 8 + lq;
#pragma unroll
        for (int ks = 0; ks < 4; ks++) {
            uint32 a[4];
            int off = lq * 33 + ks * 8 + lc;
            a[0] = __float_as_uint(qu[off]);
            a[1] = __float_as_uint(qu[off + 8 * 33]);
            a[2] = __float_as_uint(qu[off + 4]);
            a[3] = __float_as_uint(qu[off + 8 * 33 + 4]);
            uint32 b0 = __float_as_uint(buf[kn * 36 + ks * 8 + lc]);
            uint32 b1 = __float_as_uint(buf[kn * 36 + ks * 8 + lc + 4]);
            mma_tf32(cc, a, b0, b1);
        }

        {
            int kk = c * 64 + w * 8 + 2 * lc;
            unsigned int u0 = *(const unsigned short*)
                (g_idx + ((size_t)(b * LL + q0 + lq)) * LL + kk);
            unsigned int u1 = *(const unsigned short*)
                (g_idx + ((size_t)(b * LL + q0 + lq + 8)) * LL + kk);
            const float* P0 = Ps + lq * 16;
            const float* P1 = Ps + (lq + 8) * 16;
            float e00 = __expf(cc[0] + P0[u0 & 255]);
            float e01 = __expf(cc[1] + P0[(u0 >> 8) & 255]);
            float e10 = __expf(cc[2] + P1[u1 & 255]);
            float e11 = __expf(cc[3] + P1[(u1 >> 8) & 255]);
            rsum0 += e00 + e01;
            rsum1 += e10 + e11;
            *(float2*)(S + lq * 516 + kk) = make_float2(e00, e01);
            *(float2*)(S + (lq + 8) * 516 + kk) = make_float2(e10, e11);
        }

        if (c < 6)      issue(kbase + (c + 2) * 2048, (c + 2) % 3);
        else if (c == 6) issue(vbase, 2);
        else             issue(vbase + 2048, 0);
    }

    // -------- row-sum reduction + invp --------
    rsum0 += __shfl_xor_sync(0xffffffffu, rsum0, 1);
    rsum0 += __shfl_xor_sync(0xffffffffu, rsum0, 2);
    rsum1 += __shfl_xor_sync(0xffffffffu, rsum1, 1);
    rsum1 += __shfl_xor_sync(0xffffffffu, rsum1, 2);
    if (lc == 0) {
        part[lq * 8 + w] = rsum0;
        part[(lq + 8) * 8 + w] = rsum1;
    }
    __syncthreads();
    if (t < 16) {
        const float* pr = part + t * 8;
        float s = pr[0] + pr[1] + pr[2] + pr[3] + pr[4] + pr[5] + pr[6] + pr[7];
        invp[t] = 1.0f / s;
    }
    __syncthreads();

    // -------- write normalized attn --------
    float* arow = attn + ((size_t)(bh * LL + q0)) * LL;
    for (int i = t; i < 16 * 128; i += 256) {
        int r = i >> 7, c4 = (i & 127) << 2;
        float iv = invp[r];
        float4 e = *(const float4*)(S + r * 516 + c4);
        float4 o = make_float4(e.x * iv, e.y * iv, e.z * iv, e.w * iv);
        *(float4*)(arow + r * LL + c4) = o;
    }

    // -------- V loop: ctx accumulation, 8 chunks --------
    float cv[4][4];
#pragma unroll
    for (int nt = 0; nt < 4; nt++)
#pragma unroll
        for (int e = 0; e < 4; e++) cv[nt][e] = 0.0f;

#pragma unroll
    for (int c = 0; c < 8; c++) {
        if (c < 7) cp_wait<1>(); else cp_wait<0>();
        __syncthreads();
        const float* buf = bufs[(8 + c) % 3];

        uint32 a[4];
        {
            const float* ab = S + lq * 516 + c * 64 + w * 8 + lc;
            a[0] = cvt_tf32(ab[0]);
            a[1] = cvt_tf32(ab[8 * 516]);
            a[2] = cvt_tf32(ab[4]);
            a[3] = cvt_tf32(ab[8 * 516 + 4]);
        }
#pragma unroll
        for (int nt = 0; nt < 4; nt++) {
            int dn = nt * 8 + lq;
            uint32 b0 = __float_as_uint(buf[(w * 8 + lc) * 36 + dn]);
            uint32 b1 = __float_as_uint(buf[(w * 8 + lc + 4) * 36 + dn]);
            mma_tf32(cv[nt], a, b0, b1);
        }

        if (c < 6) issue(vbase + (c + 2) * 2048, (10 + c) % 3);
    }
    __syncthreads();

    // -------- two-stage cross-warp reduction: 8 partials [16][34] --------
    float* red = B0;
    if (w >= 4) {
        float* rg = red + (w - 4) * 544;
#pragma unroll
        for (int nt = 0; nt < 4; nt++) {
            int dc = nt * 8 + 2 * lc;
            *(float2*)(rg + lq * 34 + dc) = make_float2(cv[nt][0], cv[nt][1]);
            *(float2*)(rg + (lq + 8) * 34 + dc) = make_float2(cv[nt][2], cv[nt][3]);
        }
    }
    __syncthreads();
    if (w < 4) {
        float* rg = red + w * 544;
#pragma unroll
        for (int nt = 0; nt < 4; nt++) {
            int dc = nt * 8 + 2 * lc;
            float2 p0 = *(const float2*)(rg + lq * 34 + dc);
            float2 p1 = *(const float2*)(rg + (lq + 8) * 34 + dc);
            *(float2*)(rg + lq * 34 + dc) =
                make_float2(cv[nt][0] + p0.x, cv[nt][1] + p0.y);
            *(float2*)(rg + (lq + 8) * 34 + dc) =
                make_float2(cv[nt][2] + p1.x, cv[nt][3] + p1.y);
        }
    }
    __syncthreads();
    if (t < 128) {
        int q = t >> 3, d4 = (t & 7) * 4;
        float iv = invp[q];
        float o[4];
#pragma unroll
        for (int j = 0; j < 4; j++) {
            int off = q * 34 + d4 + j;
            o[j] = red[off] + red[544 + off] + red[1088 + off] + red[1632 + off];
        }
        float4 ov = make_float4(o[0] * iv, o[1] * iv, o[2] * iv, o[3] * iv);
        *(float4*)(g_ctx + ((size_t)(b * LL) + q0 + q) * DD + h * DH + d4) = ov;
    }
}

// ---------------- kernel 3: output GEMM (tf32 3-MMA, 64x64 tiles, hoisted split) ----------------
__global__ __launch_bounds__(256) void out_gemm_kernel(
        const float* __restrict__ Wo,
        const float* __restrict__ bo,
        float* __restrict__ out) {
    extern __shared__ float dsm[];
    float* Ah = dsm;
    float* Al = dsm + 4352;
    float* Bh = dsm + 8704;
    float* Bl = dsm + 13056;

    const int t = threadIdx.x;
    const int w = t >> 5, lane = t & 31;
    const int lq = lane >> 2, lc = lane & 3;
    const int wm = w >> 2, wn = w & 3;
    const int rowBase = blockIdx.y * 64;
    const int colBase = blockIdx.x * 64;

    float cc[2][2][4];
#pragma unroll
    for (int mt = 0; mt < 2; mt++)
#pragma unroll
        for (int nt = 0; nt < 2; nt++)
#pragma unroll
            for (int e = 0; e < 4; e++) cc[mt][nt][e] = 0.0f;

    for (int k0 = 0; k0 < DD; k0 += 64) {
        for (int i = t; i < 1024; i += 256) {
            int m = i >> 4, k4 = (i & 15) * 4;
            float4 x = *(const float4*)(g_ctx + (rowBase + m) * DD + k0 + k4);
            float h0 = __uint_as_float(cvt_tf32(x.x));
            float h1 = __uint_as_float(cvt_tf32(x.y));
            float h2 = __uint_as_float(cvt_tf32(x.z));
            float h3 = __uint_as_float(cvt_tf32(x.w));
            *(float4*)(Ah + m * 68 + k4) = make_float4(h0, h1, h2, h3);
            *(float4*)(Al + m * 68 + k4) = make_float4(
                __uint_as_float(cvt_tf32(x.x - h0)), __uint_as_float(cvt_tf32(x.y - h1)),
                __uint_as_float(cvt_tf32(x.z - h2)), __uint_as_float(cvt_tf32(x.w - h3)));
        }
        for (int i = t; i < 1024; i += 256) {
            int k = i >> 4, n4 = (i & 15) * 4;
            float4 x = *(const float4*)(Wo + (k0 + k) * DD + colBase + n4);
            float h0 = __uint_as_float(cvt_tf32(x.x));
            float h1 = __uint_as_float(cvt_tf32(x.y));
            float h2 = __uint_as_float(cvt_tf32(x.z));
            float h3 = __uint_as_float(cvt_tf32(x.w));
            *(float4*)(Bh + k * 68 + n4) = make_float4(h0, h1, h2, h3);
            *(float4*)(Bl + k * 68 + n4) = make_float4(
                __uint_as_float(cvt_tf32(x.x - h0)), __uint_as_float(cvt_tf32(x.y - h1)),
                __uint_as_float(cvt_tf32(x.z - h2)), __uint_as_float(cvt_tf32(x.w - h3)));
        }
        __syncthreads();
#pragma unroll
        for (int ks = 0; ks < 8; ks++) {
            uint32 ah[2][4], al[2][4];
#pragma unroll
            for (int mt = 0; mt < 2; mt++) {
                int off = (wm * 32 + mt * 16 + lq) * 68 + ks * 8 + lc;
                ah[mt][0] = __float_as_uint(Ah[off]);
                ah[mt][1] = __float_as_uint(Ah[off + 8 * 68]);
                ah[mt][2] = __float_as_uint(Ah[off + 4]);
                ah[mt][3] = __float_as_uint(Ah[off + 8 * 68 + 4]);
                al[mt][0] = __float_as_uint(Al[off]);
                al[mt][1] = __float_as_uint(Al[off + 8 * 68]);
                al[mt][2] = __float_as_uint(Al[off + 4]);
                al[mt][3] = __float_as_uint(Al[off + 8 * 68 + 4]);
            }
#pragma unroll
            for (int nt = 0; nt < 2; nt++) {
                int off = (ks * 8 + lc) * 68 + wn * 16 + nt * 8 + lq;
                uint32 bh0 = __float_as_uint(Bh[off]);
                uint32 bh1 = __float_as_uint(Bh[off + 4 * 68]);
                uint32 bl0 = __float_as_uint(Bl[off]);
                uint32 bl1 = __float_as_uint(Bl[off + 4 * 68]);
                mma_tf32(cc[0][nt], ah[0], bh0, bh1);
                mma_tf32(cc[0][nt], al[0], bh0, bh1);
                mma_tf32(cc[0][nt], ah[0], bl0, bl1);
                mma_tf32(cc[1][nt], ah[1], bh0, bh1);
                mma_tf32(cc[1][nt], al[1], bh0, bh1);
                mma_tf32(cc[1][nt], ah[1], bl0, bl1);
            }
        }
        __syncthreads();
    }

#pragma unroll
    for (int mt = 0; mt < 2; mt++) {
#pragma unroll
        for (int nt = 0; nt < 2; nt++) {
            int col0 = colBase + wn * 16 + nt * 8 + 2 * lc;
            float bx = bo[col0], by = bo[col0 + 1];
            int r0 = rowBase + wm * 32 + mt * 16 + lq;
            *(float2*)(out + r0 * DD + col0) =
                make_float2(cc[mt][nt][0] + bx, cc[mt][nt][1] + by);
            *(float2*)(out + (r0 + 8) * DD + col0) =
                make_float2(cc[mt][nt][2] + bx, cc[mt][nt][3] + by);
        }
    }
}

// ---------------- launch ----------------
extern "C" void kernel_launch(void* const* d_in, const int* in_sizes, int n_in,
                              void* d_out, int out_size) {
    const float* X         = (const float*)d_in[0];
    const void*  mask      = d_in[1];
    const int*   distances = (const int*)d_in[2];
    const float* Wq        = (const float*)d_in[3];
    const float* bq        = (const float*)d_in[4];
    const float* Wk        = (const float*)d_in[5];
    const float* bk        = (const float*)d_in[6];
    const float* Wv        = (const float*)d_in[7];
    const float* bv        = (const float*)d_in[8];
    const float* Wo        = (const float*)d_in[9];
    const float* bo        = (const float*)d_in[10];
    const float* rel_table = (const float*)d_in[11];
    const float* uvec      = (const float*)d_in[12];
    const float* vvec      = (const float*)d_in[13];

    float* out  = (float*)d_out;                       // (B,L,D)
    float* attn = (float*)d_out + BB * LL * DD;        // (B,H,L,L)

    const int gemm_smem = 17408 * 4;      // 69632 B
    const int attn_smem = 16096 * 4;      // 64384 B
    static int smem_set = 0;
    if (!smem_set) {
        cudaFuncSetAttribute(fused_prep_qkv_kernel,
                             cudaFuncAttributeMaxDynamicSharedMemorySize, gemm_smem);
        cudaFuncSetAttribute(attn_kernel,
                             cudaFuncAttributeMaxDynamicSharedMemorySize, attn_smem);
        cudaFuncSetAttribute(out_gemm_kernel,
                             cudaFuncAttributeMaxDynamicSharedMemorySize, gemm_smem);
        smem_set = 1;
    }

    fused_prep_qkv_kernel<<<384 + 1024, 256, gemm_smem>>>(
        mask, distances, X, Wq, bq, Wk, bk, Wv, bv);
    attn_kernel<<<dim3(32, 32), 256, attn_smem>>>(uvec, vvec, rel_table, attn);
    out_gemm_kernel<<<dim3(4, 32), 256, gemm_smem>>>(Wo, bo, out);
}

// round 15
// speedup vs baseline: 1.0969x; 1.0301x over previous
#include <cuda_runtime.h>
#include <cuda_bf16.h>

// Problem constants
#define BB 4
#define LL 512
#define DD 256
#define HH 8
#define DH 32
#define QK_SCALE 0.17677669529663687f  // 1/sqrt(32)

typedef unsigned long long ull;
typedef unsigned int uint32;

// ---------------- tf32 mma helpers ----------------
__device__ __forceinline__ void mma_tf32(float* c, const uint32* a, uint32 b0, uint32 b1) {
    asm volatile(
        "mma.sync.aligned.m16n8k8.row.col.f32.tf32.tf32.f32 "
        "{%0,%1,%2,%3}, {%4,%5,%6,%7}, {%8,%9}, {%0,%1,%2,%3};"
        : "+f"(c[0]), "+f"(c[1]), "+f"(c[2]), "+f"(c[3])
        : "r"(a[0]), "r"(a[1]), "r"(a[2]), "r"(a[3]), "r"(b0), "r"(b1));
}
__device__ __forceinline__ uint32 cvt_tf32(float f) {
    uint32 u; asm("cvt.rna.tf32.f32 %0, %1;" : "=r"(u) : "f"(f)); return u;
}

// ---------------- cp.async helpers ----------------
__device__ __forceinline__ void cp_async16(uint32 s, const void* g) {
    asm volatile("cp.async.cg.shared.global [%0], [%1], 16;" :: "r"(s), "l"(g));
}
__device__ __forceinline__ void cp_commit() {
    asm volatile("cp.async.commit_group;");
}
template <int N>
__device__ __forceinline__ void cp_wait() {
    asm volatile("cp.async.wait_group %0;" :: "n"(N));
}

// ---------------- device scratch ----------------
__device__ float g_q[BB * HH * LL * DH];   // scaled q, (B,H,L,DH)
__device__ float g_k[BB * HH * LL * DH];
__device__ float g_v[BB * HH * LL * DH];
__device__ float g_ctx[BB * LL * DD];      // ctx in (B,L,D) layout
__device__ unsigned char g_idx[BB * LL * LL]; // fused mask+distance bucket index

// ---------------- kernel 1: FUSED prep_idx + QKV GEMM ----------------
// grid 640 blocks: bid<384 -> qkv (z=bid/128, by=(bid%128)>>2, bx=bid&3)
//                  bid>=384 -> prep block (256 blocks, 4 uchar4 groups/thread)
__global__ __launch_bounds__(256) void fused_prep_qkv_kernel(
        const void* __restrict__ mask,
        const int* __restrict__ dist,
        const float* __restrict__ X,
        const float* __restrict__ Wq, const float* __restrict__ bq,
        const float* __restrict__ Wk, const float* __restrict__ bk,
        const float* __restrict__ Wv, const float* __restrict__ bv) {
    extern __shared__ float dsm[];
    const int bid = blockIdx.x;
    const int t = threadIdx.x;

    if (bid >= 384) {
        // ---------------- prep path (256 blocks, 1024 elems each) ----------------
        int* flags = (int*)dsm;
        const unsigned int* mw = (const unsigned int*)mask;
        if (t < 2) flags[t] = 0;
        __syncthreads();
        int f1 = 0, f2 = 0;
#pragma unroll 4
        for (int i = t; i < 4096; i += 256) {
            unsigned int w = mw[i];
            if (w == 0u || w == 1u) continue;
            if (w == 0x3F800000u) { f1 = 1; continue; }
            f2 = 1;
        }
        if (f1) atomicOr(&flags[0], 1);
        if (f2) atomicOr(&flags[1], 1);
        __syncthreads();
        const int kind = flags[1] ? 2 : (flags[0] ? 1 : 0);

        const int base = (bid - 384) * 1024 + t;
#pragma unroll
        for (int j = 0; j < 4; j++) {
            const int i = base + j * 256;
            int4 d4 = ((const int4*)dist)[i];
            int m0, m1, m2, m3;
            if (kind == 2) {
                uchar4 m = ((const uchar4*)mask)[i];
                m0 = m.x; m1 = m.y; m2 = m.z; m3 = m.w;
            } else if (kind == 1) {
                float4 m = ((const float4*)mask)[i];
                m0 = (m.x != 0.0f); m1 = (m.y != 0.0f); m2 = (m.z != 0.0f); m3 = (m.w != 0.0f);
            } else {
                int4 m = ((const int4*)mask)[i];
                m0 = m.x; m1 = m.y; m2 = m.z; m3 = m.w;
            }
            uchar4 o;
            o.x = m0 ? 12 : (unsigned char)d4.x;
            o.y = m1 ? 12 : (unsigned char)d4.y;
            o.z = m2 ? 12 : (unsigned char)d4.z;
            o.w = m3 ? 12 : (unsigned char)d4.w;
            ((uchar4*)g_idx)[i] = o;
        }
        return;
    }

    // ---------------- qkv path ----------------
    const int z = bid >> 7;
    const int rem = bid & 127;
    const int by = rem >> 2;
    const int bx = rem & 3;

    const float* W    = (z == 0) ? Wq : (z == 1 ? Wk : Wv);
    const float* bias = (z == 0) ? bq : (z == 1 ? bk : bv);
    float* out        = (z == 0) ? g_q : (z == 1 ? g_k : g_v);
    const float scale = (z == 0) ? QK_SCALE : 1.0f;

    float* Ah = dsm;                 // [m][k] 64*68
    float* Al = dsm + 4352;
    float* Bh = dsm + 8704;          // [k][n] 64*68
    float* Bl = dsm + 13056;

    const int w = t >> 5, lane = t & 31;
    const int lq = lane >> 2, lc = lane & 3;
    const int wm = w >> 2, wn = w & 3;
    const int rowBase = by * 64;
    const int colBase = bx * 64;

    float cc[2][2][4];
#pragma unroll
    for (int mt = 0; mt < 2; mt++)
#pragma unroll
        for (int nt = 0; nt < 2; nt++)
#pragma unroll
            for (int e = 0; e < 4; e++) cc[mt][nt][e] = 0.0f;

    for (int k0 = 0; k0 < DD; k0 += 64) {
        for (int i = t; i < 1024; i += 256) {
            int m = i >> 4, k4 = (i & 15) * 4;
            float4 x = *(const float4*)(X + (rowBase + m) * DD + k0 + k4);
            float h0 = __uint_as_float(cvt_tf32(x.x));
            float h1 = __uint_as_float(cvt_tf32(x.y));
            float h2 = __uint_as_float(cvt_tf32(x.z));
            float h3 = __uint_as_float(cvt_tf32(x.w));
            *(float4*)(Ah + m * 68 + k4) = make_float4(h0, h1, h2, h3);
            *(float4*)(Al + m * 68 + k4) = make_float4(
                __uint_as_float(cvt_tf32(x.x - h0)), __uint_as_float(cvt_tf32(x.y - h1)),
                __uint_as_float(cvt_tf32(x.z - h2)), __uint_as_float(cvt_tf32(x.w - h3)));
        }
        for (int i = t; i < 1024; i += 256) {
            int k = i >> 4, n4 = (i & 15) * 4;
            float4 x = *(const float4*)(W + (k0 + k) * DD + colBase + n4);
            float h0 = __uint_as_float(cvt_tf32(x.x));
            float h1 = __uint_as_float(cvt_tf32(x.y));
            float h2 = __uint_as_float(cvt_tf32(x.z));
            float h3 = __uint_as_float(cvt_tf32(x.w));
            *(float4*)(Bh + k * 68 + n4) = make_float4(h0, h1, h2, h3);
            *(float4*)(Bl + k * 68 + n4) = make_float4(
                __uint_as_float(cvt_tf32(x.x - h0)), __uint_as_float(cvt_tf32(x.y - h1)),
                __uint_as_float(cvt_tf32(x.z - h2)), __uint_as_float(cvt_tf32(x.w - h3)));
        }
        __syncthreads();
#pragma unroll
        for (int ks = 0; ks < 8; ks++) {
            uint32 ah[2][4], al[2][4];
#pragma unroll
            for (int mt = 0; mt < 2; mt++) {
                int off = (wm * 32 + mt * 16 + lq) * 68 + ks * 8 + lc;
                ah[mt][0] = __float_as_uint(Ah[off]);
                ah[mt][1] = __float_as_uint(Ah[off + 8 * 68]);
                ah[mt][2] = __float_as_uint(Ah[off + 4]);
                ah[mt][3] = __float_as_uint(Ah[off + 8 * 68 + 4]);
                al[mt][0] = __float_as_uint(Al[off]);
                al[mt][1] = __float_as_uint(Al[off + 8 * 68]);
                al[mt][2] = __float_as_uint(Al[off + 4]);
                al[mt][3] = __float_as_uint(Al[off + 8 * 68 + 4]);
            }
#pragma unroll
            for (int nt = 0; nt < 2; nt++) {
                int off = (ks * 8 + lc) * 68 + wn * 16 + nt * 8 + lq;
                uint32 bh0 = __float_as_uint(Bh[off]);
                uint32 bh1 = __float_as_uint(Bh[off + 4 * 68]);
                uint32 bl0 = __float_as_uint(Bl[off]);
                uint32 bl1 = __float_as_uint(Bl[off + 4 * 68]);
                mma_tf32(cc[0][nt], ah[0], bh0, bh1);
                mma_tf32(cc[0][nt], al[0], bh0, bh1);
                mma_tf32(cc[0][nt], ah[0], bl0, bl1);
                mma_tf32(cc[1][nt], ah[1], bh0, bh1);
                mma_tf32(cc[1][nt], al[1], bh0, bh1);
                mma_tf32(cc[1][nt], ah[1], bl0, bl1);
            }
        }
        __syncthreads();
    }

#pragma unroll
    for (int mt = 0; mt < 2; mt++) {
#pragma unroll
        for (int nt = 0; nt < 2; nt++) {
            int col0 = colBase + wn * 16 + nt * 8 + 2 * lc;
            int h = col0 >> 5, d = col0 & 31;
            float bx2 = bias[col0], by2 = bias[col0 + 1];
            int r0 = rowBase + wm * 32 + mt * 16 + lq;
            {
                int b = r0 >> 9, l = r0 & 511;
                float2 o = make_float2((cc[mt][nt][0] + bx2) * scale,
                                       (cc[mt][nt][1] + by2) * scale);
                *(float2*)(out + (((b * HH + h) * LL) + l) * DH + d) = o;
            }
            {
                int r1 = r0 + 8;
                int b = r1 >> 9, l = r1 & 511;
                float2 o = make_float2((cc[mt][nt][2] + bx2) * scale,
                                       (cc[mt][nt][3] + by2) * scale);
                *(float2*)(out + (((b * HH + h) * LL) + l) * DH + d) = o;
            }
        }
    }
}

// ---------------- kernel 2: fused attention (R12 version: 128-chunks, double buffer) ----------------
// smem floats: S 8256 | KB0 4608 | KB1 4608 | qu 528 | Ps 256 | invp 16 | part 128 = 18400
__global__ __launch_bounds__(256, 3) void attn_kernel(
        const float* __restrict__ uvec,
        const float* __restrict__ vvec,
        const float* __restrict__ rel_table,
        float* __restrict__ attn) {
    extern __shared__ float sm[];
    float* S    = sm;                    // [16][516]
    float* KB0  = sm + 8256;             // [128][36]
    float* KB1  = sm + 12864;            // [128][36]
    float* qu   = sm + 17472;            // [16][33]
    float* Ps   = qu + 528;              // [16][16]
    float* invp = Ps + 256;              // [16]
    float* part = invp + 16;             // [16][8]

    const int bh = blockIdx.y;
    const int b = bh >> 3, h = bh & 7;
    const int q0 = blockIdx.x * 16;
    const int t = threadIdx.x;
    const int w = t >> 5;
    const int lane = t & 31;
    const int lq = lane >> 2;
    const int lc = lane & 3;

    const float* kbase = g_k + (size_t)bh * LL * DH;
    const float* vbase = g_v + (size_t)bh * LL * DH;
    const uint32 sKB0 = (uint32)__cvta_generic_to_shared(KB0);
    const uint32 sKB1 = (uint32)__cvta_generic_to_shared(KB1);

    // prefetch K chunk 0 into KB0
    {
#pragma unroll
        for (int i = 0; i < 4; i++) {
            int idx = t + i * 256;
            int k = idx >> 3, seg = idx & 7;
            cp_async16(sKB0 + k * 144 + seg * 16, kbase + k * 32 + seg * 4);
        }
        cp_commit();
    }

    // -------- phase 0: qu = q+v, table slice (in KB1), P --------
    if (t < 128) {
        int q = t >> 3, d4 = (t & 7) * 4;
        float4 qv = *(const float4*)(g_q + ((size_t)bh * LL + q0 + q) * DH + d4);
        float4 vv = *(const float4*)(vvec + h * DH + d4);
        qu[q * 33 + d4 + 0] = qv.x + vv.x;
        qu[q * 33 + d4 + 1] = qv.y + vv.y;
        qu[q * 33 + d4 + 2] = qv.z + vv.z;
        qu[q * 33 + d4 + 3] = qv.w + vv.w;
    }
    float* tbl = KB1;   // [12][33]
    for (int i = t; i < 384; i += 256) {
        int bu = i >> 5, d = i & 31;
        tbl[bu * 33 + d] = rel_table[bu * DD + h * DH + d];
    }
    __syncthreads();
    if (t < 192) {
        int q = t / 12, bu = t - q * 12;
        const float* qp = qu + q * 33;
        const float* tp = tbl + bu * 33;
        float s = 0.0f;
#pragma unroll
        for (int d = 0; d < 32; d++) s = fmaf(qp[d], tp[d], s);
        Ps[q * 16 + bu] = s;
    }
    if (t < 16) Ps[t * 16 + 12] = -1e18f;
    __syncthreads();
    if (t < 128) {
        int q = t >> 3, d4 = (t & 7) * 4;
        float4 uu = *(const float4*)(uvec + h * DH + d4);
        float4 vv = *(const float4*)(vvec + h * DH + d4);
        qu[q * 33 + d4 + 0] += uu.x - vv.x;
        qu[q * 33 + d4 + 1] += uu.y - vv.y;
        qu[q * 33 + d4 + 2] += uu.z - vv.z;
        qu[q * 33 + d4 + 3] += uu.w - vv.w;
    }

    // -------- phase 1: scores + exp + partial row sums (max-free) --------
    float rsum0 = 0.0f, rsum1 = 0.0f;
#pragma unroll 1
    for (int c = 0; c < 4; c++) {
        __syncthreads();
        if (c < 3) {
            uint32 dst = ((c + 1) & 1) ? sKB1 : sKB0;
            const float* src = kbase + (c + 1) * 128 * 32;
#pragma unroll
            for (int i = 0; i < 4; i++) {
                int idx = t + i * 256;
                int k = idx >> 3, seg = idx & 7;
                cp_async16(dst + k * 144 + seg * 16, src + k * 32 + seg * 4);
            }
            cp_commit();
        } else {
#pragma unroll
            for (int i = 0; i < 4; i++) {
                int idx = t + i * 256;
                int k = idx >> 3, seg = idx & 7;
                cp_async16(sKB0 + k * 144 + seg * 16, vbase + k * 32 + seg * 4);
            }
            cp_commit();
        }
        cp_wait<1>();
        __syncthreads();

        const float* buf = (c & 1) ? KB1 : KB0;
        float cc[2][4];
#pragma unroll
        for (int nt = 0; nt < 2; nt++)
#pragma unroll
            for (int e = 0; e < 4; e++) cc[nt][e] = 0.0f;

#pragma unroll
        for (int ks = 0; ks < 4; ks++) {
            uint32 a[4];
            {
                int off = lq * 33 + ks * 8 + lc;
                a[0] = __float_as_uint(qu[off]);
                a[1] = __float_as_uint(qu[off + 8 * 33]);
                a[2] = __float_as_uint(qu[off + 4]);
                a[3] = __float_as_uint(qu[off + 8 * 33 + 4]);
            }
#pragma unroll
            for (int nt = 0; nt < 2; nt++) {
                int kn = w * 16 + nt * 8 + lq;
                uint32 b0 = __float_as_uint(buf[kn * 36 + ks * 8 + lc]);
                uint32 b1 = __float_as_uint(buf[kn * 36 + ks * 8 + lc + 4]);
                mma_tf32(cc[nt], a, b0, b1);
            }
        }

        int kc = c * 128;
#pragma unroll
        for (int nt = 0; nt < 2; nt++) {
            int kk = kc + w * 16 + nt * 8 + 2 * lc;
            unsigned int u0 = *(const unsigned short*)
                (g_idx + ((size_t)(b * LL + q0 + lq)) * LL + kk);
            unsigned int u1 = *(const unsigned short*)
                (g_idx + ((size_t)(b * LL + q0 + lq + 8)) * LL + kk);
            const float* P0 = Ps + lq * 16;
            const float* P1 = Ps + (lq + 8) * 16;
            float e00 = __expf(cc[nt][0] + P0[u0 & 255]);
            float e01 = __expf(cc[nt][1] + P0[(u0 >> 8) & 255]);
            float e10 = __expf(cc[nt][2] + P1[u1 & 255]);
            float e11 = __expf(cc[nt][3] + P1[(u1 >> 8) & 255]);
            rsum0 += e00 + e01;
            rsum1 += e10 + e11;
            *(float2*)(S + lq * 516 + kk) = make_float2(e00, e01);
            *(float2*)(S + (lq + 8) * 516 + kk) = make_float2(e10, e11);
        }
    }

    // reduce row sums
    rsum0 += __shfl_xor_sync(0xffffffffu, rsum0, 1);
    rsum0 += __shfl_xor_sync(0xffffffffu, rsum0, 2);
    rsum1 += __shfl_xor_sync(0xffffffffu, rsum1, 1);
    rsum1 += __shfl_xor_sync(0xffffffffu, rsum1, 2);
    if (lc == 0) {
        part[lq * 8 + w] = rsum0;
        part[(lq + 8) * 8 + w] = rsum1;
    }
    __syncthreads();
    if (t < 16) {
        const float* pr = part + t * 8;
        float s = pr[0] + pr[1] + pr[2] + pr[3] + pr[4] + pr[5] + pr[6] + pr[7];
        invp[t] = 1.0f / s;
    }
    __syncthreads();

    // -------- phase 2: write normalized attn --------
    float* arow = attn + ((size_t)(bh * LL + q0)) * LL;
    for (int i = t; i < 16 * 128; i += 256) {
        int r = i >> 7, c4 = (i & 127) << 2;
        float iv = invp[r];
        float4 e = *(const float4*)(S + r * 516 + c4);
        float4 o = make_float4(e.x * iv, e.y * iv, e.z * iv, e.w * iv);
        *(float4*)(arow + r * LL + c4) = o;
    }

    // -------- phase 3: ctx = S @ V, double-buffered V --------
    float cv[4][4];
#pragma unroll
    for (int nt = 0; nt < 4; nt++)
#pragma unroll
        for (int e = 0; e < 4; e++) cv[nt][e] = 0.0f;

#pragma unroll 1
    for (int c = 0; c < 4; c++) {
        __syncthreads();
        if (c < 3) {
            uint32 dst = ((c + 1) & 1) ? sKB1 : sKB0;
            const float* src = vbase + (c + 1) * 128 * 32;
#pragma unroll
            for (int i = 0; i < 4; i++) {
                int idx = t + i * 256;
                int k = idx >> 3, seg = idx & 7;
                cp_async16(dst + k * 144 + seg * 16, src + k * 32 + seg * 4);
            }
            cp_commit();
            cp_wait<1>();
        } else {
            cp_wait<0>();
        }
        __syncthreads();

        const float* buf = (c & 1) ? KB1 : KB0;
#pragma unroll
        for (int ks = 0; ks < 2; ks++) {
            int kb = w * 16 + ks * 8;
            uint32 a[4];
            {
                const float* ab = S + lq * 516 + c * 128 + kb + lc;
                a[0] = cvt_tf32(ab[0]);
                a[1] = cvt_tf32(ab[8 * 516]);
                a[2] = cvt_tf32(ab[4]);
                a[3] = cvt_tf32(ab[8 * 516 + 4]);
            }
#pragma unroll
            for (int nt = 0; nt < 4; nt++) {
                int dn = nt * 8 + lq;
                uint32 b0 = __float_as_uint(buf[(kb + lc) * 36 + dn]);
                uint32 b1 = __float_as_uint(buf[(kb + lc + 4) * 36 + dn]);
                mma_tf32(cv[nt], a, b0, b1);
            }
        }
    }
    __syncthreads();

    // two-stage cross-warp reduction: 8 partials [16][34] in KB0
    float* red = KB0;
    if (w >= 4) {
        float* rg = red + (w - 4) * 544;
#pragma unroll
        for (int nt = 0; nt < 4; nt++) {
            int dc = nt * 8 + 2 * lc;
            *(float2*)(rg + lq * 34 + dc) = make_float2(cv[nt][0], cv[nt][1]);
            *(float2*)(rg + (lq + 8) * 34 + dc) = make_float2(cv[nt][2], cv[nt][3]);
        }
    }
    __syncthreads();
    if (w < 4) {
        float* rg = red + w * 544;
#pragma unroll
        for (int nt = 0; nt < 4; nt++) {
            int dc = nt * 8 + 2 * lc;
            float2 p0 = *(const float2*)(rg + lq * 34 + dc);
            float2 p1 = *(const float2*)(rg + (lq + 8) * 34 + dc);
            *(float2*)(rg + lq * 34 + dc) =
                make_float2(cv[nt][0] + p0.x, cv[nt][1] + p0.y);
            *(float2*)(rg + (lq + 8) * 34 + dc) =
                make_float2(cv[nt][2] + p1.x, cv[nt][3] + p1.y);
        }
    }
    __syncthreads();
    if (t < 128) {
        int q = t >> 3, d4 = (t & 7) * 4;
        float iv = invp[q];
        float o[4];
#pragma unroll
        for (int j = 0; j < 4; j++) {
            int off = q * 34 + d4 + j;
            o[j] = red[off] + red[544 + off] + red[1088 + off] + red[1632 + off];
        }
        float4 ov = make_float4(o[0] * iv, o[1] * iv, o[2] * iv, o[3] * iv);
        *(float4*)(g_ctx + ((size_t)(b * LL) + q0 + q) * DD + h * DH + d4) = ov;
    }
}

// ---------------- kernel 3: output GEMM (tf32 3-MMA, 64x64 tiles, hoisted split) ----------------
__global__ __launch_bounds__(256) void out_gemm_kernel(
        const float* __restrict__ Wo,
        const float* __restrict__ bo,
        float* __restrict__ out) {
    extern __shared__ float dsm[];
    float* Ah = dsm;
    float* Al = dsm + 4352;
    float* Bh = dsm + 8704;
    float* Bl = dsm + 13056;

    const int t = threadIdx.x;
    const int w = t >> 5, lane = t & 31;
    const int lq = lane >> 2, lc = lane & 3;
    const int wm = w >> 2, wn = w & 3;
    const int rowBase = blockIdx.y * 64;
    const int colBase = blockIdx.x * 64;

    float cc[2][2][4];
#pragma unroll
    for (int mt = 0; mt < 2; mt++)
#pragma unroll
        for (int nt = 0; nt < 2; nt++)
#pragma unroll
            for (int e = 0; e < 4; e++) cc[mt][nt][e] = 0.0f;

    for (int k0 = 0; k0 < DD; k0 += 64) {
        for (int i = t; i < 1024; i += 256) {
            int m = i >> 4, k4 = (i & 15) * 4;
            float4 x = *(const float4*)(g_ctx + (rowBase + m) * DD + k0 + k4);
            float h0 = __uint_as_float(cvt_tf32(x.x));
            float h1 = __uint_as_float(cvt_tf32(x.y));
            float h2 = __uint_as_float(cvt_tf32(x.z));
            float h3 = __uint_as_float(cvt_tf32(x.w));
            *(float4*)(Ah + m * 68 + k4) = make_float4(h0, h1, h2, h3);
            *(float4*)(Al + m * 68 + k4) = make_float4(
                __uint_as_float(cvt_tf32(x.x - h0)), __uint_as_float(cvt_tf32(x.y - h1)),
                __uint_as_float(cvt_tf32(x.z - h2)), __uint_as_float(cvt_tf32(x.w - h3)));
        }
        for (int i = t; i < 1024; i += 256) {
            int k = i >> 4, n4 = (i & 15) * 4;
            float4 x = *(const float4*)(Wo + (k0 + k) * DD + colBase + n4);
            float h0 = __uint_as_float(cvt_tf32(x.x));
            float h1 = __uint_as_float(cvt_tf32(x.y));
            float h2 = __uint_as_float(cvt_tf32(x.z));
            float h3 = __uint_as_float(cvt_tf32(x.w));
            *(float4*)(Bh + k * 68 + n4) = make_float4(h0, h1, h2, h3);
            *(float4*)(Bl + k * 68 + n4) = make_float4(
                __uint_as_float(cvt_tf32(x.x - h0)), __uint_as_float(cvt_tf32(x.y - h1)),
                __uint_as_float(cvt_tf32(x.z - h2)), __uint_as_float(cvt_tf32(x.w - h3)));
        }
        __syncthreads();
#pragma unroll
        for (int ks = 0; ks < 8; ks++) {
            uint32 ah[2][4], al[2][4];
#pragma unroll
            for (int mt = 0; mt < 2; mt++) {
                int off = (wm * 32 + mt * 16 + lq) * 68 + ks * 8 + lc;
                ah[mt][0] = __float_as_uint(Ah[off]);
                ah[mt][1] = __float_as_uint(Ah[off + 8 * 68]);
                ah[mt][2] = __float_as_uint(Ah[off + 4]);
                ah[mt][3] = __float_as_uint(Ah[off + 8 * 68 + 4]);
                al[mt][0] = __float_as_uint(Al[off]);
                al[mt][1] = __float_as_uint(Al[off + 8 * 68]);
                al[mt][2] = __float_as_uint(Al[off + 4]);
                al[mt][3] = __float_as_uint(Al[off + 8 * 68 + 4]);
            }
#pragma unroll
            for (int nt = 0; nt < 2; nt++) {
                int off = (ks * 8 + lc) * 68 + wn * 16 + nt * 8 + lq;
                uint32 bh0 = __float_as_uint(Bh[off]);
                uint32 bh1 = __float_as_uint(Bh[off + 4 * 68]);
                uint32 bl0 = __float_as_uint(Bl[off]);
                uint32 bl1 = __float_as_uint(Bl[off + 4 * 68]);
                mma_tf32(cc[0][nt], ah[0], bh0, bh1);
                mma_tf32(cc[0][nt], al[0], bh0, bh1);
                mma_tf32(cc[0][nt], ah[0], bl0, bl1);
                mma_tf32(cc[1][nt], ah[1], bh0, bh1);
                mma_tf32(cc[1][nt], al[1], bh0, bh1);
                mma_tf32(cc[1][nt], ah[1], bl0, bl1);
            }
        }
        __syncthreads();
    }

#pragma unroll
    for (int mt = 0; mt < 2; mt++) {
#pragma unroll
        for (int nt = 0; nt < 2; nt++) {
            int col0 = colBase + wn * 16 + nt * 8 + 2 * lc;
            float bx = bo[col0], by = bo[col0 + 1];
            int r0 = rowBase + wm * 32 + mt * 16 + lq;
            *(float2*)(out + r0 * DD + col0) =
                make_float2(cc[mt][nt][0] + bx, cc[mt][nt][1] + by);
            *(float2*)(out + (r0 + 8) * DD + col0) =
                make_float2(cc[mt][nt][2] + bx, cc[mt][nt][3] + by);
        }
    }
}

// ---------------- launch ----------------
extern "C" void kernel_launch(void* const* d_in, const int* in_sizes, int n_in,
                              void* d_out, int out_size) {
    const float* X         = (const float*)d_in[0];
    const void*  mask      = d_in[1];
    const int*   distances = (const int*)d_in[2];
    const float* Wq        = (const float*)d_in[3];
    const float* bq        = (const float*)d_in[4];
    const float* Wk        = (const float*)d_in[5];
    const float* bk        = (const float*)d_in[6];
    const float* Wv        = (const float*)d_in[7];
    const float* bv        = (const float*)d_in[8];
    const float* Wo        = (const float*)d_in[9];
    const float* bo        = (const float*)d_in[10];
    const float* rel_table = (const float*)d_in[11];
    const float* uvec      = (const float*)d_in[12];
    const float* vvec      = (const float*)d_in[13];

    float* out  = (float*)d_out;                       // (B,L,D)
    float* attn = (float*)d_out + BB * LL * DD;        // (B,H,L,L)

    const int gemm_smem = 17408 * 4;      // 69632 B
    const int attn_smem = 18400 * 4;      // 73600 B
    static int smem_set = 0;
    if (!smem_set) {
        cudaFuncSetAttribute(fused_prep_qkv_kernel,
                             cudaFuncAttributeMaxDynamicSharedMemorySize, gemm_smem);
        cudaFuncSetAttribute(attn_kernel,
                             cudaFuncAttributeMaxDynamicSharedMemorySize, attn_smem);
        cudaFuncSetAttribute(out_gemm_kernel,
                             cudaFuncAttributeMaxDynamicSharedMemorySize, gemm_smem);
        smem_set = 1;
    }

    fused_prep_qkv_kernel<<<384 + 256, 256, gemm_smem>>>(
        mask, distances, X, Wq, bq, Wk, bk, Wv, bv);
    attn_kernel<<<dim3(32, 32), 256, attn_smem>>>(uvec, vvec, rel_table, attn);
    out_gemm_kernel<<<dim3(4, 32), 256, gemm_smem>>>(Wo, bo, out);
}

// round 16
// speedup vs baseline: 1.1339x; 1.0338x over previous
#include <cuda_runtime.h>
#include <cuda_bf16.h>

// Problem constants
#define BB 4
#define LL 512
#define DD 256
#define HH 8
#define DH 32
#define QK_SCALE 0.17677669529663687f  // 1/sqrt(32)

typedef unsigned long long ull;
typedef unsigned int uint32;

// ---------------- tf32 mma helpers ----------------
__device__ __forceinline__ void mma_tf32(float* c, const uint32* a, uint32 b0, uint32 b1) {
    asm volatile(
        "mma.sync.aligned.m16n8k8.row.col.f32.tf32.tf32.f32 "
        "{%0,%1,%2,%3}, {%4,%5,%6,%7}, {%8,%9}, {%0,%1,%2,%3};"
        : "+f"(c[0]), "+f"(c[1]), "+f"(c[2]), "+f"(c[3])
        : "r"(a[0]), "r"(a[1]), "r"(a[2]), "r"(a[3]), "r"(b0), "r"(b1));
}
__device__ __forceinline__ uint32 cvt_tf32(float f) {
    uint32 u; asm("cvt.rna.tf32.f32 %0, %1;" : "=r"(u) : "f"(f)); return u;
}

// ---------------- cp.async helpers ----------------
__device__ __forceinline__ void cp_async16(uint32 s, const void* g) {
    asm volatile("cp.async.cg.shared.global [%0], [%1], 16;" :: "r"(s), "l"(g));
}
__device__ __forceinline__ void cp_commit() {
    asm volatile("cp.async.commit_group;");
}
template <int N>
__device__ __forceinline__ void cp_wait() {
    asm volatile("cp.async.wait_group %0;" :: "n"(N));
}

// ---------------- device scratch ----------------
__device__ float g_q[BB * HH * LL * DH];   // scaled q, (B,H,L,DH)
__device__ float g_k[BB * HH * LL * DH];
__device__ float g_v[BB * HH * LL * DH];
__device__ float g_ctx[BB * LL * DD];      // ctx in (B,L,D) layout
__device__ unsigned char g_idx[BB * LL * LL]; // fused mask+distance bucket index

// ---------------- kernel 1: FUSED prep_idx + QKV GEMM (R12 config) ----------------
// grid 1408 blocks: bid<384 -> qkv (z=bid/128, by=(bid%128)>>2, bx=bid&3)
//                   bid>=384 -> prep block (1024 blocks, 1 uchar4 group/thread)
__global__ __launch_bounds__(256) void fused_prep_qkv_kernel(
        const void* __restrict__ mask,
        const int* __restrict__ dist,
        const float* __restrict__ X,
        const float* __restrict__ Wq, const float* __restrict__ bq,
        const float* __restrict__ Wk, const float* __restrict__ bk,
        const float* __restrict__ Wv, const float* __restrict__ bv) {
    extern __shared__ float dsm[];
    const int bid = blockIdx.x;
    const int t = threadIdx.x;

    if (bid >= 384) {
        // ---------------- prep path ----------------
        int* flags = (int*)dsm;
        const unsigned int* mw = (const unsigned int*)mask;
        if (t < 2) flags[t] = 0;
        __syncthreads();
        int f1 = 0, f2 = 0;
#pragma unroll 4
        for (int i = t; i < 4096; i += 256) {
            unsigned int w = mw[i];
            if (w == 0u || w == 1u) continue;
            if (w == 0x3F800000u) { f1 = 1; continue; }
            f2 = 1;
        }
        if (f1) atomicOr(&flags[0], 1);
        if (f2) atomicOr(&flags[1], 1);
        __syncthreads();
        const int kind = flags[1] ? 2 : (flags[0] ? 1 : 0);

        const int i = (bid - 384) * 256 + t;
        int4 d4 = ((const int4*)dist)[i];
        int m0, m1, m2, m3;
        if (kind == 2) {
            uchar4 m = ((const uchar4*)mask)[i];
            m0 = m.x; m1 = m.y; m2 = m.z; m3 = m.w;
        } else if (kind == 1) {
            float4 m = ((const float4*)mask)[i];
            m0 = (m.x != 0.0f); m1 = (m.y != 0.0f); m2 = (m.z != 0.0f); m3 = (m.w != 0.0f);
        } else {
            int4 m = ((const int4*)mask)[i];
            m0 = m.x; m1 = m.y; m2 = m.z; m3 = m.w;
        }
        uchar4 o;
        o.x = m0 ? 12 : (unsigned char)d4.x;
        o.y = m1 ? 12 : (unsigned char)d4.y;
        o.z = m2 ? 12 : (unsigned char)d4.z;
        o.w = m3 ? 12 : (unsigned char)d4.w;
        ((uchar4*)g_idx)[i] = o;
        return;
    }

    // ---------------- qkv path ----------------
    const int z = bid >> 7;
    const int rem = bid & 127;
    const int by = rem >> 2;
    const int bx = rem & 3;

    const float* W    = (z == 0) ? Wq : (z == 1 ? Wk : Wv);
    const float* bias = (z == 0) ? bq : (z == 1 ? bk : bv);
    float* out        = (z == 0) ? g_q : (z == 1 ? g_k : g_v);
    const float scale = (z == 0) ? QK_SCALE : 1.0f;

    float* Ah = dsm;                 // [m][k] 64*68
    float* Al = dsm + 4352;
    float* Bh = dsm + 8704;          // [k][n] 64*68
    float* Bl = dsm + 13056;

    const int w = t >> 5, lane = t & 31;
    const int lq = lane >> 2, lc = lane & 3;
    const int wm = w >> 2, wn = w & 3;
    const int rowBase = by * 64;
    const int colBase = bx * 64;

    float cc[2][2][4];
#pragma unroll
    for (int mt = 0; mt < 2; mt++)
#pragma unroll
        for (int nt = 0; nt < 2; nt++)
#pragma unroll
            for (int e = 0; e < 4; e++) cc[mt][nt][e] = 0.0f;

    for (int k0 = 0; k0 < DD; k0 += 64) {
        for (int i = t; i < 1024; i += 256) {
            int m = i >> 4, k4 = (i & 15) * 4;
            float4 x = *(const float4*)(X + (rowBase + m) * DD + k0 + k4);
            float h0 = __uint_as_float(cvt_tf32(x.x));
            float h1 = __uint_as_float(cvt_tf32(x.y));
            float h2 = __uint_as_float(cvt_tf32(x.z));
            float h3 = __uint_as_float(cvt_tf32(x.w));
            *(float4*)(Ah + m * 68 + k4) = make_float4(h0, h1, h2, h3);
            *(float4*)(Al + m * 68 + k4) = make_float4(
                __uint_as_float(cvt_tf32(x.x - h0)), __uint_as_float(cvt_tf32(x.y - h1)),
                __uint_as_float(cvt_tf32(x.z - h2)), __uint_as_float(cvt_tf32(x.w - h3)));
        }
        for (int i = t; i < 1024; i += 256) {
            int k = i >> 4, n4 = (i & 15) * 4;
            float4 x = *(const float4*)(W + (k0 + k) * DD + colBase + n4);
            float h0 = __uint_as_float(cvt_tf32(x.x));
            float h1 = __uint_as_float(cvt_tf32(x.y));
            float h2 = __uint_as_float(cvt_tf32(x.z));
            float h3 = __uint_as_float(cvt_tf32(x.w));
            *(float4*)(Bh + k * 68 + n4) = make_float4(h0, h1, h2, h3);
            *(float4*)(Bl + k * 68 + n4) = make_float4(
                __uint_as_float(cvt_tf32(x.x - h0)), __uint_as_float(cvt_tf32(x.y - h1)),
                __uint_as_float(cvt_tf32(x.z - h2)), __uint_as_float(cvt_tf32(x.w - h3)));
        }
        __syncthreads();
#pragma unroll
        for (int ks = 0; ks < 8; ks++) {
            uint32 ah[2][4], al[2][4];
#pragma unroll
            for (int mt = 0; mt < 2; mt++) {
                int off = (wm * 32 + mt * 16 + lq) * 68 + ks * 8 + lc;
                ah[mt][0] = __float_as_uint(Ah[off]);
                ah[mt][1] = __float_as_uint(Ah[off + 8 * 68]);
                ah[mt][2] = __float_as_uint(Ah[off + 4]);
                ah[mt][3] = __float_as_uint(Ah[off + 8 * 68 + 4]);
                al[mt][0] = __float_as_uint(Al[off]);
                al[mt][1] = __float_as_uint(Al[off + 8 * 68]);
                al[mt][2] = __float_as_uint(Al[off + 4]);
                al[mt][3] = __float_as_uint(Al[off + 8 * 68 + 4]);
            }
#pragma unroll
            for (int nt = 0; nt < 2; nt++) {
                int off = (ks * 8 + lc) * 68 + wn * 16 + nt * 8 + lq;
                uint32 bh0 = __float_as_uint(Bh[off]);
                uint32 bh1 = __float_as_uint(Bh[off + 4 * 68]);
                uint32 bl0 = __float_as_uint(Bl[off]);
                uint32 bl1 = __float_as_uint(Bl[off + 4 * 68]);
                mma_tf32(cc[0][nt], ah[0], bh0, bh1);
                mma_tf32(cc[0][nt], al[0], bh0, bh1);
                mma_tf32(cc[0][nt], ah[0], bl0, bl1);
                mma_tf32(cc[1][nt], ah[1], bh0, bh1);
                mma_tf32(cc[1][nt], al[1], bh0, bh1);
                mma_tf32(cc[1][nt], ah[1], bl0, bl1);
            }
        }
        __syncthreads();
    }

#pragma unroll
    for (int mt = 0; mt < 2; mt++) {
#pragma unroll
        for (int nt = 0; nt < 2; nt++) {
            int col0 = colBase + wn * 16 + nt * 8 + 2 * lc;
            int h = col0 >> 5, d = col0 & 31;
            float bx2 = bias[col0], by2 = bias[col0 + 1];
            int r0 = rowBase + wm * 32 + mt * 16 + lq;
            {
                int b = r0 >> 9, l = r0 & 511;
                float2 o = make_float2((cc[mt][nt][0] + bx2) * scale,
                                       (cc[mt][nt][1] + by2) * scale);
                *(float2*)(out + (((b * HH + h) * LL) + l) * DH + d) = o;
            }
            {
                int r1 = r0 + 8;
                int b = r1 >> 9, l = r1 & 511;
                float2 o = make_float2((cc[mt][nt][2] + bx2) * scale,
                                       (cc[mt][nt][3] + by2) * scale);
                *(float2*)(out + (((b * HH + h) * LL) + l) * DH + d) = o;
            }
        }
    }
}

// ---------------- kernel 2: fused attention (attn-write folded into V loop) ----------------
// smem floats: S 8256 | KB0 4608 | KB1 4608 | qu 528 | Ps 256 | invp 16 | part 128 = 18400
__global__ __launch_bounds__(256, 3) void attn_kernel(
        const float* __restrict__ uvec,
        const float* __restrict__ vvec,
        const float* __restrict__ rel_table,
        float* __restrict__ attn) {
    extern __shared__ float sm[];
    float* S    = sm;                    // [16][516]
    float* KB0  = sm + 8256;             // [128][36]
    float* KB1  = sm + 12864;            // [128][36]
    float* qu   = sm + 17472;            // [16][33]
    float* Ps   = qu + 528;              // [16][16]
    float* invp = Ps + 256;              // [16]
    float* part = invp + 16;             // [16][8]

    const int bh = blockIdx.y;
    const int b = bh >> 3, h = bh & 7;
    const int q0 = blockIdx.x * 16;
    const int t = threadIdx.x;
    const int w = t >> 5;
    const int lane = t & 31;
    const int lq = lane >> 2;
    const int lc = lane & 3;

    const float* kbase = g_k + (size_t)bh * LL * DH;
    const float* vbase = g_v + (size_t)bh * LL * DH;
    const uint32 sKB0 = (uint32)__cvta_generic_to_shared(KB0);
    const uint32 sKB1 = (uint32)__cvta_generic_to_shared(KB1);

    // prefetch K chunk 0 into KB0
    {
#pragma unroll
        for (int i = 0; i < 4; i++) {
            int idx = t + i * 256;
            int k = idx >> 3, seg = idx & 7;
            cp_async16(sKB0 + k * 144 + seg * 16, kbase + k * 32 + seg * 4);
        }
        cp_commit();
    }

    // -------- phase 0: qu = q+v, table slice (in KB1), P --------
    if (t < 128) {
        int q = t >> 3, d4 = (t & 7) * 4;
        float4 qv = *(const float4*)(g_q + ((size_t)bh * LL + q0 + q) * DH + d4);
        float4 vv = *(const float4*)(vvec + h * DH + d4);
        qu[q * 33 + d4 + 0] = qv.x + vv.x;
        qu[q * 33 + d4 + 1] = qv.y + vv.y;
        qu[q * 33 + d4 + 2] = qv.z + vv.z;
        qu[q * 33 + d4 + 3] = qv.w + vv.w;
    }
    float* tbl = KB1;   // [12][33]
    for (int i = t; i < 384; i += 256) {
        int bu = i >> 5, d = i & 31;
        tbl[bu * 33 + d] = rel_table[bu * DD + h * DH + d];
    }
    __syncthreads();
    if (t < 192) {
        int q = t / 12, bu = t - q * 12;
        const float* qp = qu + q * 33;
        const float* tp = tbl + bu * 33;
        float s = 0.0f;
#pragma unroll
        for (int d = 0; d < 32; d++) s = fmaf(qp[d], tp[d], s);
        Ps[q * 16 + bu] = s;
    }
    if (t < 16) Ps[t * 16 + 12] = -1e18f;
    __syncthreads();
    if (t < 128) {
        int q = t >> 3, d4 = (t & 7) * 4;
        float4 uu = *(const float4*)(uvec + h * DH + d4);
        float4 vv = *(const float4*)(vvec + h * DH + d4);
        qu[q * 33 + d4 + 0] += uu.x - vv.x;
        qu[q * 33 + d4 + 1] += uu.y - vv.y;
        qu[q * 33 + d4 + 2] += uu.z - vv.z;
        qu[q * 33 + d4 + 3] += uu.w - vv.w;
    }

    // -------- phase 1: scores + exp + partial row sums (max-free) --------
    float rsum0 = 0.0f, rsum1 = 0.0f;
#pragma unroll 1
    for (int c = 0; c < 4; c++) {
        __syncthreads();
        if (c < 3) {
            uint32 dst = ((c + 1) & 1) ? sKB1 : sKB0;
            const float* src = kbase + (c + 1) * 128 * 32;
#pragma unroll
            for (int i = 0; i < 4; i++) {
                int idx = t + i * 256;
                int k = idx >> 3, seg = idx & 7;
                cp_async16(dst + k * 144 + seg * 16, src + k * 32 + seg * 4);
            }
            cp_commit();
        } else {
#pragma unroll
            for (int i = 0; i < 4; i++) {
                int idx = t + i * 256;
                int k = idx >> 3, seg = idx & 7;
                cp_async16(sKB0 + k * 144 + seg * 16, vbase + k * 32 + seg * 4);
            }
            cp_commit();
        }
        cp_wait<1>();
        __syncthreads();

        const float* buf = (c & 1) ? KB1 : KB0;
        float cc[2][4];
#pragma unroll
        for (int nt = 0; nt < 2; nt++)
#pragma unroll
            for (int e = 0; e < 4; e++) cc[nt][e] = 0.0f;

#pragma unroll
        for (int ks = 0; ks < 4; ks++) {
            uint32 a[4];
            {
                int off = lq * 33 + ks * 8 + lc;
                a[0] = __float_as_uint(qu[off]);
                a[1] = __float_as_uint(qu[off + 8 * 33]);
                a[2] = __float_as_uint(qu[off + 4]);
                a[3] = __float_as_uint(qu[off + 8 * 33 + 4]);
            }
#pragma unroll
            for (int nt = 0; nt < 2; nt++) {
                int kn = w * 16 + nt * 8 + lq;
                uint32 b0 = __float_as_uint(buf[kn * 36 + ks * 8 + lc]);
                uint32 b1 = __float_as_uint(buf[kn * 36 + ks * 8 + lc + 4]);
                mma_tf32(cc[nt], a, b0, b1);
            }
        }

        int kc = c * 128;
#pragma unroll
        for (int nt = 0; nt < 2; nt++) {
            int kk = kc + w * 16 + nt * 8 + 2 * lc;
            unsigned int u0 = *(const unsigned short*)
                (g_idx + ((size_t)(b * LL + q0 + lq)) * LL + kk);
            unsigned int u1 = *(const unsigned short*)
                (g_idx + ((size_t)(b * LL + q0 + lq + 8)) * LL + kk);
            const float* P0 = Ps + lq * 16;
            const float* P1 = Ps + (lq + 8) * 16;
            float e00 = __expf(cc[nt][0] + P0[u0 & 255]);
            float e01 = __expf(cc[nt][1] + P0[(u0 >> 8) & 255]);
            float e10 = __expf(cc[nt][2] + P1[u1 & 255]);
            float e11 = __expf(cc[nt][3] + P1[(u1 >> 8) & 255]);
            rsum0 += e00 + e01;
            rsum1 += e10 + e11;
            *(float2*)(S + lq * 516 + kk) = make_float2(e00, e01);
            *(float2*)(S + (lq + 8) * 516 + kk) = make_float2(e10, e11);
        }
    }

    // reduce row sums
    rsum0 += __shfl_xor_sync(0xffffffffu, rsum0, 1);
    rsum0 += __shfl_xor_sync(0xffffffffu, rsum0, 2);
    rsum1 += __shfl_xor_sync(0xffffffffu, rsum1, 1);
    rsum1 += __shfl_xor_sync(0xffffffffu, rsum1, 2);
    if (lc == 0) {
        part[lq * 8 + w] = rsum0;
        part[(lq + 8) * 8 + w] = rsum1;
    }
    __syncthreads();
    if (t < 16) {
        const float* pr = part + t * 8;
        float s = pr[0] + pr[1] + pr[2] + pr[3] + pr[4] + pr[5] + pr[6] + pr[7];
        invp[t] = 1.0f / s;
    }
    __syncthreads();

    // -------- phase 3: ctx = S @ V, double-buffered V; attn write folded in --------
    float* arow = attn + ((size_t)(bh * LL + q0)) * LL;
    float cv[4][4];
#pragma unroll
    for (int nt = 0; nt < 4; nt++)
#pragma unroll
        for (int e = 0; e < 4; e++) cv[nt][e] = 0.0f;

#pragma unroll 1
    for (int c = 0; c < 4; c++) {
        __syncthreads();
        if (c < 3) {
            uint32 dst = ((c + 1) & 1) ? sKB1 : sKB0;
            const float* src = vbase + (c + 1) * 128 * 32;
#pragma unroll
            for (int i = 0; i < 4; i++) {
                int idx = t + i * 256;
                int k = idx >> 3, seg = idx & 7;
                cp_async16(dst + k * 144 + seg * 16, src + k * 32 + seg * 4);
            }
            cp_commit();
            cp_wait<1>();
        } else {
            cp_wait<0>();
        }
        __syncthreads();

        // write normalized attn for this chunk's columns (overlaps MMA/idle)
#pragma unroll
        for (int i = 0; i < 2; i++) {
            int idx = t + i * 256;               // 0..511
            int r = idx >> 5, c4 = (idx & 31) * 4 + c * 128;
            float iv = invp[r];
            float4 e = *(const float4*)(S + r * 516 + c4);
            float4 o = make_float4(e.x * iv, e.y * iv, e.z * iv, e.w * iv);
            *(float4*)(arow + r * LL + c4) = o;
        }

        const float* buf = (c & 1) ? KB1 : KB0;
#pragma unroll
        for (int ks = 0; ks < 2; ks++) {
            int kb = w * 16 + ks * 8;
            uint32 a[4];
            {
                const float* ab = S + lq * 516 + c * 128 + kb + lc;
                a[0] = cvt_tf32(ab[0]);
                a[1] = cvt_tf32(ab[8 * 516]);
                a[2] = cvt_tf32(ab[4]);
                a[3] = cvt_tf32(ab[8 * 516 + 4]);
            }
#pragma unroll
            for (int nt = 0; nt < 4; nt++) {
                int dn = nt * 8 + lq;
                uint32 b0 = __float_as_uint(buf[(kb + lc) * 36 + dn]);
                uint32 b1 = __float_as_uint(buf[(kb + lc + 4) * 36 + dn]);
                mma_tf32(cv[nt], a, b0, b1);
            }
        }
    }
    __syncthreads();

    // two-stage cross-warp reduction: 8 partials [16][34] in KB0
    float* red = KB0;
    if (w >= 4) {
        float* rg = red + (w - 4) * 544;
#pragma unroll
        for (int nt = 0; nt < 4; nt++) {
            int dc = nt * 8 + 2 * lc;
            *(float2*)(rg + lq * 34 + dc) = make_float2(cv[nt][0], cv[nt][1]);
            *(float2*)(rg + (lq + 8) * 34 + dc) = make_float2(cv[nt][2], cv[nt][3]);
        }
    }
    __syncthreads();
    if (w < 4) {
        float* rg = red + w * 544;
#pragma unroll
        for (int nt = 0; nt < 4; nt++) {
            int dc = nt * 8 + 2 * lc;
            float2 p0 = *(const float2*)(rg + lq * 34 + dc);
            float2 p1 = *(const float2*)(rg + (lq + 8) * 34 + dc);
            *(float2*)(rg + lq * 34 + dc) =
                make_float2(cv[nt][0] + p0.x, cv[nt][1] + p0.y);
            *(float2*)(rg + (lq + 8) * 34 + dc) =
                make_float2(cv[nt][2] + p1.x, cv[nt][3] + p1.y);
        }
    }
    __syncthreads();
    if (t < 128) {
        int q = t >> 3, d4 = (t & 7) * 4;
        float iv = invp[q];
        float o[4];
#pragma unroll
        for (int j = 0; j < 4; j++) {
            int off = q * 34 + d4 + j;
            o[j] = red[off] + red[544 + off] + red[1088 + off] + red[1632 + off];
        }
        float4 ov = make_float4(o[0] * iv, o[1] * iv, o[2] * iv, o[3] * iv);
        *(float4*)(g_ctx + ((size_t)(b * LL) + q0 + q) * DD + h * DH + d4) = ov;
    }
}

// ---------------- kernel 3: output GEMM (tf32 3-MMA, 64x64 tiles, hoisted split) ----------------
__global__ __launch_bounds__(256) void out_gemm_kernel(
        const float* __restrict__ Wo,
        const float* __restrict__ bo,
        float* __restrict__ out) {
    extern __shared__ float dsm[];
    float* Ah = dsm;
    float* Al = dsm + 4352;
    float* Bh = dsm + 8704;
    float* Bl = dsm + 13056;

    const int t = threadIdx.x;
    const int w = t >> 5, lane = t & 31;
    const int lq = lane >> 2, lc = lane & 3;
    const int wm = w >> 2, wn = w & 3;
    const int rowBase = blockIdx.y * 64;
    const int colBase = blockIdx.x * 64;

    float cc[2][2][4];
#pragma unroll
    for (int mt = 0; mt < 2; mt++)
#pragma unroll
        for (int nt = 0; nt < 2; nt++)
#pragma unroll
            for (int e = 0; e < 4; e++) cc[mt][nt][e] = 0.0f;

    for (int k0 = 0; k0 < DD; k0 += 64) {
        for (int i = t; i < 1024; i += 256) {
            int m = i >> 4, k4 = (i & 15) * 4;
            float4 x = *(const float4*)(g_ctx + (rowBase + m) * DD + k0 + k4);
            float h0 = __uint_as_float(cvt_tf32(x.x));
            float h1 = __uint_as_float(cvt_tf32(x.y));
            float h2 = __uint_as_float(cvt_tf32(x.z));
            float h3 = __uint_as_float(cvt_tf32(x.w));
            *(float4*)(Ah + m * 68 + k4) = make_float4(h0, h1, h2, h3);
            *(float4*)(Al + m * 68 + k4) = make_float4(
                __uint_as_float(cvt_tf32(x.x - h0)), __uint_as_float(cvt_tf32(x.y - h1)),
                __uint_as_float(cvt_tf32(x.z - h2)), __uint_as_float(cvt_tf32(x.w - h3)));
        }
        for (int i = t; i < 1024; i += 256) {
            int k = i >> 4, n4 = (i & 15) * 4;
            float4 x = *(const float4*)(Wo + (k0 + k) * DD + colBase + n4);
            float h0 = __uint_as_float(cvt_tf32(x.x));
            float h1 = __uint_as_float(cvt_tf32(x.y));
            float h2 = __uint_as_float(cvt_tf32(x.z));
            float h3 = __uint_as_float(cvt_tf32(x.w));
            *(float4*)(Bh + k * 68 + n4) = make_float4(h0, h1, h2, h3);
            *(float4*)(Bl + k * 68 + n4) = make_float4(
                __uint_as_float(cvt_tf32(x.x - h0)), __uint_as_float(cvt_tf32(x.y - h1)),
                __uint_as_float(cvt_tf32(x.z - h2)), __uint_as_float(cvt_tf32(x.w - h3)));
        }
        __syncthreads();
#pragma unroll
        for (int ks = 0; ks < 8; ks++) {
            uint32 ah[2][4], al[2][4];
#pragma unroll
            for (int mt = 0; mt < 2; mt++) {
                int off = (wm * 32 + mt * 16 + lq) * 68 + ks * 8 + lc;
                ah[mt][0] = __float_as_uint(Ah[off]);
                ah[mt][1] = __float_as_uint(Ah[off + 8 * 68]);
                ah[mt][2] = __float_as_uint(Ah[off + 4]);
                ah[mt][3] = __float_as_uint(Ah[off + 8 * 68 + 4]);
                al[mt][0] = __float_as_uint(Al[off]);
                al[mt][1] = __float_as_uint(Al[off + 8 * 68]);
                al[mt][2] = __float_as_uint(Al[off + 4]);
                al[mt][3] = __float_as_uint(Al[off + 8 * 68 + 4]);
            }
#pragma unroll
            for (int nt = 0; nt < 2; nt++) {
                int off = (ks * 8 + lc) * 68 + wn * 16 + nt * 8 + lq;
                uint32 bh0 = __float_as_uint(Bh[off]);
                uint32 bh1 = __float_as_uint(Bh[off + 4 * 68]);
                uint32 bl0 = __float_as_uint(Bl[off]);
                uint32 bl1 = __float_as_uint(Bl[off + 4 * 68]);
                mma_tf32(cc[0][nt], ah[0], bh0, bh1);
                mma_tf32(cc[0][nt], al[0], bh0, bh1);
                mma_tf32(cc[0][nt], ah[0], bl0, bl1);
                mma_tf32(cc[1][nt], ah[1], bh0, bh1);
                mma_tf32(cc[1][nt], al[1], bh0, bh1);
                mma_tf32(cc[1][nt], ah[1], bl0, bl1);
            }
        }
        __syncthreads();
    }

#pragma unroll
    for (int mt = 0; mt < 2; mt++) {
#pragma unroll
        for (int nt = 0; nt < 2; nt++) {
            int col0 = colBase + wn * 16 + nt * 8 + 2 * lc;
            float bx = bo[col0], by = bo[col0 + 1];
            int r0 = rowBase + wm * 32 + mt * 16 + lq;
            *(float2*)(out + r0 * DD + col0) =
                make_float2(cc[mt][nt][0] + bx, cc[mt][nt][1] + by);
            *(float2*)(out + (r0 + 8) * DD + col0) =
                make_float2(cc[mt][nt][2] + bx, cc[mt][nt][3] + by);
        }
    }
}

// ---------------- launch ----------------
extern "C" void kernel_launch(void* const* d_in, const int* in_sizes, int n_in,
                              void* d_out, int out_size) {
    const float* X         = (const float*)d_in[0];
    const void*  mask      = d_in[1];
    const int*   distances = (const int*)d_in[2];
    const float* Wq        = (const float*)d_in[3];
    const float* bq        = (const float*)d_in[4];
    const float* Wk        = (const float*)d_in[5];
    const float* bk        = (const float*)d_in[6];
    const float* Wv        = (const float*)d_in[7];
    const float* bv        = (const float*)d_in[8];
    const float* Wo        = (const float*)d_in[9];
    const float* bo        = (const float*)d_in[10];
    const float* rel_table = (const float*)d_in[11];
    const float* uvec      = (const float*)d_in[12];
    const float* vvec      = (const float*)d_in[13];

    float* out  = (float*)d_out;                       // (B,L,D)
    float* attn = (float*)d_out + BB * LL * DD;        // (B,H,L,L)

    const int gemm_smem = 17408 * 4;      // 69632 B
    const int attn_smem = 18400 * 4;      // 73600 B
    static int smem_set = 0;
    if (!smem_set) {
        cudaFuncSetAttribute(fused_prep_qkv_kernel,
                             cudaFuncAttributeMaxDynamicSharedMemorySize, gemm_smem);
        cudaFuncSetAttribute(attn_kernel,
                             cudaFuncAttributeMaxDynamicSharedMemorySize, attn_smem);
        cudaFuncSetAttribute(out_gemm_kernel,
                             cudaFuncAttributeMaxDynamicSharedMemorySize, gemm_smem);
        smem_set = 1;
    }

    fused_prep_qkv_kernel<<<384 + 1024, 256, gemm_smem>>>(
        mask, distances, X, Wq, bq, Wk, bk, Wv, bv);
    attn_kernel<<<dim3(32, 32), 256, attn_smem>>>(uvec, vvec, rel_table, attn);
    out_gemm_kernel<<<dim3(4, 32), 256, gemm_smem>>>(Wo, bo, out);
}

// round 17
// speedup vs baseline: 1.1455x; 1.0102x over previous
#include <cuda_runtime.h>
#include <cuda_bf16.h>

// Problem constants
#define BB 4
#define LL 512
#define DD 256
#define HH 8
#define DH 32
#define QK_SCALE 0.17677669529663687f  // 1/sqrt(32)

typedef unsigned long long ull;
typedef unsigned int uint32;

// ---------------- tf32 mma helpers ----------------
__device__ __forceinline__ void mma_tf32(float* c, const uint32* a, uint32 b0, uint32 b1) {
    asm volatile(
        "mma.sync.aligned.m16n8k8.row.col.f32.tf32.tf32.f32 "
        "{%0,%1,%2,%3}, {%4,%5,%6,%7}, {%8,%9}, {%0,%1,%2,%3};"
        : "+f"(c[0]), "+f"(c[1]), "+f"(c[2]), "+f"(c[3])
        : "r"(a[0]), "r"(a[1]), "r"(a[2]), "r"(a[3]), "r"(b0), "r"(b1));
}
__device__ __forceinline__ uint32 cvt_tf32(float f) {
    uint32 u; asm("cvt.rna.tf32.f32 %0, %1;" : "=r"(u) : "f"(f)); return u;
}

// ---------------- cp.async helpers ----------------
__device__ __forceinline__ void cp_async16(uint32 s, const void* g) {
    asm volatile("cp.async.cg.shared.global [%0], [%1], 16;" :: "r"(s), "l"(g));
}
__device__ __forceinline__ void cp_commit() {
    asm volatile("cp.async.commit_group;");
}
template <int N>
__device__ __forceinline__ void cp_wait() {
    asm volatile("cp.async.wait_group %0;" :: "n"(N));
}

// ---------------- device scratch ----------------
__device__ float g_q[BB * HH * LL * DH];   // scaled q, (B,H,L,DH)
__device__ float g_k[BB * HH * LL * DH];
__device__ float g_v[BB * HH * LL * DH];
__device__ float g_ctx[BB * LL * DD];      // ctx in (B,L,D) layout
__device__ unsigned char g_idx[BB * LL * LL]; // fused mask+distance bucket index

// ---------------- kernel 1: FUSED prep_idx + QKV GEMM (R12 config) ----------------
__global__ __launch_bounds__(256) void fused_prep_qkv_kernel(
        const void* __restrict__ mask,
        const int* __restrict__ dist,
        const float* __restrict__ X,
        const float* __restrict__ Wq, const float* __restrict__ bq,
        const float* __restrict__ Wk, const float* __restrict__ bk,
        const float* __restrict__ Wv, const float* __restrict__ bv) {
    extern __shared__ float dsm[];
    const int bid = blockIdx.x;
    const int t = threadIdx.x;

    if (bid >= 384) {
        // ---------------- prep path ----------------
        int* flags = (int*)dsm;
        const unsigned int* mw = (const unsigned int*)mask;
        if (t < 2) flags[t] = 0;
        __syncthreads();
        int f1 = 0, f2 = 0;
#pragma unroll 4
        for (int i = t; i < 4096; i += 256) {
            unsigned int w = mw[i];
            if (w == 0u || w == 1u) continue;
            if (w == 0x3F800000u) { f1 = 1; continue; }
            f2 = 1;
        }
        if (f1) atomicOr(&flags[0], 1);
        if (f2) atomicOr(&flags[1], 1);
        __syncthreads();
        const int kind = flags[1] ? 2 : (flags[0] ? 1 : 0);

        const int i = (bid - 384) * 256 + t;
        int4 d4 = ((const int4*)dist)[i];
        int m0, m1, m2, m3;
        if (kind == 2) {
            uchar4 m = ((const uchar4*)mask)[i];
            m0 = m.x; m1 = m.y; m2 = m.z; m3 = m.w;
        } else if (kind == 1) {
            float4 m = ((const float4*)mask)[i];
            m0 = (m.x != 0.0f); m1 = (m.y != 0.0f); m2 = (m.z != 0.0f); m3 = (m.w != 0.0f);
        } else {
            int4 m = ((const int4*)mask)[i];
            m0 = m.x; m1 = m.y; m2 = m.z; m3 = m.w;
        }
        uchar4 o;
        o.x = m0 ? 12 : (unsigned char)d4.x;
        o.y = m1 ? 12 : (unsigned char)d4.y;
        o.z = m2 ? 12 : (unsigned char)d4.z;
        o.w = m3 ? 12 : (unsigned char)d4.w;
        ((uchar4*)g_idx)[i] = o;
        return;
    }

    // ---------------- qkv path ----------------
    const int z = bid >> 7;
    const int rem = bid & 127;
    const int by = rem >> 2;
    const int bx = rem & 3;

    const float* W    = (z == 0) ? Wq : (z == 1 ? Wk : Wv);
    const float* bias = (z == 0) ? bq : (z == 1 ? bk : bv);
    float* out        = (z == 0) ? g_q : (z == 1 ? g_k : g_v);
    const float scale = (z == 0) ? QK_SCALE : 1.0f;

    float* Ah = dsm;                 // [m][k] 64*68
    float* Al = dsm + 4352;
    float* Bh = dsm + 8704;          // [k][n] 64*68
    float* Bl = dsm + 13056;

    const int w = t >> 5, lane = t & 31;
    const int lq = lane >> 2, lc = lane & 3;
    const int wm = w >> 2, wn = w & 3;
    const int rowBase = by * 64;
    const int colBase = bx * 64;

    float cc[2][2][4];
#pragma unroll
    for (int mt = 0; mt < 2; mt++)
#pragma unroll
        for (int nt = 0; nt < 2; nt++)
#pragma unroll
            for (int e = 0; e < 4; e++) cc[mt][nt][e] = 0.0f;

    for (int k0 = 0; k0 < DD; k0 += 64) {
        for (int i = t; i < 1024; i += 256) {
            int m = i >> 4, k4 = (i & 15) * 4;
            float4 x = *(const float4*)(X + (rowBase + m) * DD + k0 + k4);
            float h0 = __uint_as_float(cvt_tf32(x.x));
            float h1 = __uint_as_float(cvt_tf32(x.y));
            float h2 = __uint_as_float(cvt_tf32(x.z));
            float h3 = __uint_as_float(cvt_tf32(x.w));
            *(float4*)(Ah + m * 68 + k4) = make_float4(h0, h1, h2, h3);
            *(float4*)(Al + m * 68 + k4) = make_float4(
                __uint_as_float(cvt_tf32(x.x - h0)), __uint_as_float(cvt_tf32(x.y - h1)),
                __uint_as_float(cvt_tf32(x.z - h2)), __uint_as_float(cvt_tf32(x.w - h3)));
        }
        for (int i = t; i < 1024; i += 256) {
            int k = i >> 4, n4 = (i & 15) * 4;
            float4 x = *(const float4*)(W + (k0 + k) * DD + colBase + n4);
            float h0 = __uint_as_float(cvt_tf32(x.x));
            float h1 = __uint_as_float(cvt_tf32(x.y));
            float h2 = __uint_as_float(cvt_tf32(x.z));
            float h3 = __uint_as_float(cvt_tf32(x.w));
            *(float4*)(Bh + k * 68 + n4) = make_float4(h0, h1, h2, h3);
            *(float4*)(Bl + k * 68 + n4) = make_float4(
                __uint_as_float(cvt_tf32(x.x - h0)), __uint_as_float(cvt_tf32(x.y - h1)),
                __uint_as_float(cvt_tf32(x.z - h2)), __uint_as_float(cvt_tf32(x.w - h3)));
        }
        __syncthreads();
#pragma unroll
        for (int ks = 0; ks < 8; ks++) {
            uint32 ah[2][4], al[2][4];
#pragma unroll
            for (int mt = 0; mt < 2; mt++) {
                int off = (wm * 32 + mt * 16 + lq) * 68 + ks * 8 + lc;
                ah[mt][0] = __float_as_uint(Ah[off]);
                ah[mt][1] = __float_as_uint(Ah[off + 8 * 68]);
                ah[mt][2] = __float_as_uint(Ah[off + 4]);
                ah[mt][3] = __float_as_uint(Ah[off + 8 * 68 + 4]);
                al[mt][0] = __float_as_uint(Al[off]);
                al[mt][1] = __float_as_uint(Al[off + 8 * 68]);
                al[mt][2] = __float_as_uint(Al[off + 4]);
                al[mt][3] = __float_as_uint(Al[off + 8 * 68 + 4]);
            }
#pragma unroll
            for (int nt = 0; nt < 2; nt++) {
                int off = (ks * 8 + lc) * 68 + wn * 16 + nt * 8 + lq;
                uint32 bh0 = __float_as_uint(Bh[off]);
                uint32 bh1 = __float_as_uint(Bh[off + 4 * 68]);
                uint32 bl0 = __float_as_uint(Bl[off]);
                uint32 bl1 = __float_as_uint(Bl[off + 4 * 68]);
                mma_tf32(cc[0][nt], ah[0], bh0, bh1);
                mma_tf32(cc[0][nt], al[0], bh0, bh1);
                mma_tf32(cc[0][nt], ah[0], bl0, bl1);
                mma_tf32(cc[1][nt], ah[1], bh0, bh1);
                mma_tf32(cc[1][nt], al[1], bh0, bh1);
                mma_tf32(cc[1][nt], ah[1], bl0, bl1);
            }
        }
        __syncthreads();
    }

#pragma unroll
    for (int mt = 0; mt < 2; mt++) {
#pragma unroll
        for (int nt = 0; nt < 2; nt++) {
            int col0 = colBase + wn * 16 + nt * 8 + 2 * lc;
            int h = col0 >> 5, d = col0 & 31;
            float bx2 = bias[col0], by2 = bias[col0 + 1];
            int r0 = rowBase + wm * 32 + mt * 16 + lq;
            {
                int b = r0 >> 9, l = r0 & 511;
                float2 o = make_float2((cc[mt][nt][0] + bx2) * scale,
                                       (cc[mt][nt][1] + by2) * scale);
                *(float2*)(out + (((b * HH + h) * LL) + l) * DH + d) = o;
            }
            {
                int r1 = r0 + 8;
                int b = r1 >> 9, l = r1 & 511;
                float2 o = make_float2((cc[mt][nt][2] + bx2) * scale,
                                       (cc[mt][nt][3] + by2) * scale);
                *(float2*)(out + (((b * HH + h) * LL) + l) * DH + d) = o;
            }
        }
    }
}

// ---------------- kernel 2: fused attention (R16: attn-write folded into V loop) ----------------
// smem floats: S 8256 | KB0 4608 | KB1 4608 | qu 528 | Ps 256 | invp 16 | part 128 = 18400
__global__ __launch_bounds__(256, 3) void attn_kernel(
        const float* __restrict__ uvec,
        const float* __restrict__ vvec,
        const float* __restrict__ rel_table,
        float* __restrict__ attn) {
    extern __shared__ float sm[];
    float* S    = sm;                    // [16][516]
    float* KB0  = sm + 8256;             // [128][36]
    float* KB1  = sm + 12864;            // [128][36]
    float* qu   = sm + 17472;            // [16][33]
    float* Ps   = qu + 528;              // [16][16]
    float* invp = Ps + 256;              // [16]
    float* part = invp + 16;             // [16][8]

    const int bh = blockIdx.y;
    const int b = bh >> 3, h = bh & 7;
    const int q0 = blockIdx.x * 16;
    const int t = threadIdx.x;
    const int w = t >> 5;
    const int lane = t & 31;
    const int lq = lane >> 2;
    const int lc = lane & 3;

    const float* kbase = g_k + (size_t)bh * LL * DH;
    const float* vbase = g_v + (size_t)bh * LL * DH;
    const uint32 sKB0 = (uint32)__cvta_generic_to_shared(KB0);
    const uint32 sKB1 = (uint32)__cvta_generic_to_shared(KB1);

    // prefetch K chunk 0 into KB0
    {
#pragma unroll
        for (int i = 0; i < 4; i++) {
            int idx = t + i * 256;
            int k = idx >> 3, seg = idx & 7;
            cp_async16(sKB0 + k * 144 + seg * 16, kbase + k * 32 + seg * 4);
        }
        cp_commit();
    }

    // -------- phase 0: qu = q+v, table slice (in KB1), P --------
    if (t < 128) {
        int q = t >> 3, d4 = (t & 7) * 4;
        float4 qv = *(const float4*)(g_q + ((size_t)bh * LL + q0 + q) * DH + d4);
        float4 vv = *(const float4*)(vvec + h * DH + d4);
        qu[q * 33 + d4 + 0] = qv.x + vv.x;
        qu[q * 33 + d4 + 1] = qv.y + vv.y;
        qu[q * 33 + d4 + 2] = qv.z + vv.z;
        qu[q * 33 + d4 + 3] = qv.w + vv.w;
    }
    float* tbl = KB1;   // [12][33]
    for (int i = t; i < 384; i += 256) {
        int bu = i >> 5, d = i & 31;
        tbl[bu * 33 + d] = rel_table[bu * DD + h * DH + d];
    }
    __syncthreads();
    if (t < 192) {
        int q = t / 12, bu = t - q * 12;
        const float* qp = qu + q * 33;
        const float* tp = tbl + bu * 33;
        float s = 0.0f;
#pragma unroll
        for (int d = 0; d < 32; d++) s = fmaf(qp[d], tp[d], s);
        Ps[q * 16 + bu] = s;
    }
    if (t < 16) Ps[t * 16 + 12] = -1e18f;
    __syncthreads();
    if (t < 128) {
        int q = t >> 3, d4 = (t & 7) * 4;
        float4 uu = *(const float4*)(uvec + h * DH + d4);
        float4 vv = *(const float4*)(vvec + h * DH + d4);
        qu[q * 33 + d4 + 0] += uu.x - vv.x;
        qu[q * 33 + d4 + 1] += uu.y - vv.y;
        qu[q * 33 + d4 + 2] += uu.z - vv.z;
        qu[q * 33 + d4 + 3] += uu.w - vv.w;
    }

    // -------- phase 1: scores + exp + partial row sums (max-free) --------
    float rsum0 = 0.0f, rsum1 = 0.0f;
#pragma unroll 1
    for (int c = 0; c < 4; c++) {
        __syncthreads();
        if (c < 3) {
            uint32 dst = ((c + 1) & 1) ? sKB1 : sKB0;
            const float* src = kbase + (c + 1) * 128 * 32;
#pragma unroll
            for (int i = 0; i < 4; i++) {
                int idx = t + i * 256;
                int k = idx >> 3, seg = idx & 7;
                cp_async16(dst + k * 144 + seg * 16, src + k * 32 + seg * 4);
            }
            cp_commit();
        } else {
#pragma unroll
            for (int i = 0; i < 4; i++) {
                int idx = t + i * 256;
                int k = idx >> 3, seg = idx & 7;
                cp_async16(sKB0 + k * 144 + seg * 16, vbase + k * 32 + seg * 4);
            }
            cp_commit();
        }
        cp_wait<1>();
        __syncthreads();

        const float* buf = (c & 1) ? KB1 : KB0;
        float cc[2][4];
#pragma unroll
        for (int nt = 0; nt < 2; nt++)
#pragma unroll
            for (int e = 0; e < 4; e++) cc[nt][e] = 0.0f;

#pragma unroll
        for (int ks = 0; ks < 4; ks++) {
            uint32 a[4];
            {
                int off = lq * 33 + ks * 8 + lc;
                a[0] = __float_as_uint(qu[off]);
                a[1] = __float_as_uint(qu[off + 8 * 33]);
                a[2] = __float_as_uint(qu[off + 4]);
                a[3] = __float_as_uint(qu[off + 8 * 33 + 4]);
            }
#pragma unroll
            for (int nt = 0; nt < 2; nt++) {
                int kn = w * 16 + nt * 8 + lq;
                uint32 b0 = __float_as_uint(buf[kn * 36 + ks * 8 + lc]);
                uint32 b1 = __float_as_uint(buf[kn * 36 + ks * 8 + lc + 4]);
                mma_tf32(cc[nt], a, b0, b1);
            }
        }

        int kc = c * 128;
#pragma unroll
        for (int nt = 0; nt < 2; nt++) {
            int kk = kc + w * 16 + nt * 8 + 2 * lc;
            unsigned int u0 = *(const unsigned short*)
                (g_idx + ((size_t)(b * LL + q0 + lq)) * LL + kk);
            unsigned int u1 = *(const unsigned short*)
                (g_idx + ((size_t)(b * LL + q0 + lq + 8)) * LL + kk);
            const float* P0 = Ps + lq * 16;
            const float* P1 = Ps + (lq + 8) * 16;
            float e00 = __expf(cc[nt][0] + P0[u0 & 255]);
            float e01 = __expf(cc[nt][1] + P0[(u0 >> 8) & 255]);
            float e10 = __expf(cc[nt][2] + P1[u1 & 255]);
            float e11 = __expf(cc[nt][3] + P1[(u1 >> 8) & 255]);
            rsum0 += e00 + e01;
            rsum1 += e10 + e11;
            *(float2*)(S + lq * 516 + kk) = make_float2(e00, e01);
            *(float2*)(S + (lq + 8) * 516 + kk) = make_float2(e10, e11);
        }
    }

    // reduce row sums
    rsum0 += __shfl_xor_sync(0xffffffffu, rsum0, 1);
    rsum0 += __shfl_xor_sync(0xffffffffu, rsum0, 2);
    rsum1 += __shfl_xor_sync(0xffffffffu, rsum1, 1);
    rsum1 += __shfl_xor_sync(0xffffffffu, rsum1, 2);
    if (lc == 0) {
        part[lq * 8 + w] = rsum0;
        part[(lq + 8) * 8 + w] = rsum1;
    }
    __syncthreads();
    if (t < 16) {
        const float* pr = part + t * 8;
        float s = pr[0] + pr[1] + pr[2] + pr[3] + pr[4] + pr[5] + pr[6] + pr[7];
        invp[t] = 1.0f / s;
    }
    __syncthreads();

    // -------- phase 3: ctx = S @ V, double-buffered V; attn write folded in --------
    float* arow = attn + ((size_t)(bh * LL + q0)) * LL;
    float cv[4][4];
#pragma unroll
    for (int nt = 0; nt < 4; nt++)
#pragma unroll
        for (int e = 0; e < 4; e++) cv[nt][e] = 0.0f;

#pragma unroll 1
    for (int c = 0; c < 4; c++) {
        __syncthreads();
        if (c < 3) {
            uint32 dst = ((c + 1) & 1) ? sKB1 : sKB0;
            const float* src = vbase + (c + 1) * 128 * 32;
#pragma unroll
            for (int i = 0; i < 4; i++) {
                int idx = t + i * 256;
                int k = idx >> 3, seg = idx & 7;
                cp_async16(dst + k * 144 + seg * 16, src + k * 32 + seg * 4);
            }
            cp_commit();
            cp_wait<1>();
        } else {
            cp_wait<0>();
        }
        __syncthreads();

        // write normalized attn for this chunk's columns (overlaps MMA/idle)
#pragma unroll
        for (int i = 0; i < 2; i++) {
            int idx = t + i * 256;               // 0..511
            int r = idx >> 5, c4 = (idx & 31) * 4 + c * 128;
            float iv = invp[r];
            float4 e = *(const float4*)(S + r * 516 + c4);
            float4 o = make_float4(e.x * iv, e.y * iv, e.z * iv, e.w * iv);
            *(float4*)(arow + r * LL + c4) = o;
        }

        const float* buf = (c & 1) ? KB1 : KB0;
#pragma unroll
        for (int ks = 0; ks < 2; ks++) {
            int kb = w * 16 + ks * 8;
            uint32 a[4];
            {
                const float* ab = S + lq * 516 + c * 128 + kb + lc;
                a[0] = cvt_tf32(ab[0]);
                a[1] = cvt_tf32(ab[8 * 516]);
                a[2] = cvt_tf32(ab[4]);
                a[3] = cvt_tf32(ab[8 * 516 + 4]);
            }
#pragma unroll
            for (int nt = 0; nt < 4; nt++) {
                int dn = nt * 8 + lq;
                uint32 b0 = __float_as_uint(buf[(kb + lc) * 36 + dn]);
                uint32 b1 = __float_as_uint(buf[(kb + lc + 4) * 36 + dn]);
                mma_tf32(cv[nt], a, b0, b1);
            }
        }
    }
    __syncthreads();

    // two-stage cross-warp reduction: 8 partials [16][34] in KB0
    float* red = KB0;
    if (w >= 4) {
        float* rg = red + (w - 4) * 544;
#pragma unroll
        for (int nt = 0; nt < 4; nt++) {
            int dc = nt * 8 + 2 * lc;
            *(float2*)(rg + lq * 34 + dc) = make_float2(cv[nt][0], cv[nt][1]);
            *(float2*)(rg + (lq + 8) * 34 + dc) = make_float2(cv[nt][2], cv[nt][3]);
        }
    }
    __syncthreads();
    if (w < 4) {
        float* rg = red + w * 544;
#pragma unroll
        for (int nt = 0; nt < 4; nt++) {
            int dc = nt * 8 + 2 * lc;
            float2 p0 = *(const float2*)(rg + lq * 34 + dc);
            float2 p1 = *(const float2*)(rg + (lq + 8) * 34 + dc);
            *(float2*)(rg + lq * 34 + dc) =
                make_float2(cv[nt][0] + p0.x, cv[nt][1] + p0.y);
            *(float2*)(rg + (lq + 8) * 34 + dc) =
                make_float2(cv[nt][2] + p1.x, cv[nt][3] + p1.y);
        }
    }
    __syncthreads();
    if (t < 128) {
        int q = t >> 3, d4 = (t & 7) * 4;
        float iv = invp[q];
        float o[4];
#pragma unroll
        for (int j = 0; j < 4; j++) {
            int off = q * 34 + d4 + j;
            o[j] = red[off] + red[544 + off] + red[1088 + off] + red[1632 + off];
        }
        float4 ov = make_float4(o[0] * iv, o[1] * iv, o[2] * iv, o[3] * iv);
        *(float4*)(g_ctx + ((size_t)(b * LL) + q0 + q) * DD + h * DH + d4) = ov;
    }
}

// ---------------- kernel 3: output GEMM (tf32 3-MMA, 32x64 tiles, grid 256) ----------------
// smem: Ah[32][68] Al[32][68] Bh[64][68] Bl[64][68] = 13056 floats
__global__ __launch_bounds__(256) void out_gemm_kernel(
        const float* __restrict__ Wo,
        const float* __restrict__ bo,
        float* __restrict__ out) {
    extern __shared__ float dsm[];
    float* Ah = dsm;                 // [32][68]
    float* Al = dsm + 2176;
    float* Bh = dsm + 4352;          // [64][68]
    float* Bl = dsm + 8704;

    const int t = threadIdx.x;
    const int w = t >> 5, lane = t & 31;
    const int lq = lane >> 2, lc = lane & 3;
    const int wm = w >> 2, wn = w & 3;       // 2 x 4 warps, warp tile 16x16
    const int rowBase = blockIdx.y * 32;
    const int colBase = blockIdx.x * 64;

    float cc[2][4];
#pragma unroll
    for (int nt = 0; nt < 2; nt++)
#pragma unroll
        for (int e = 0; e < 4; e++) cc[nt][e] = 0.0f;

    for (int k0 = 0; k0 < DD; k0 += 64) {
        for (int i = t; i < 512; i += 256) {
            int m = i >> 4, k4 = (i & 15) * 4;
            float4 x = *(const float4*)(g_ctx + (rowBase + m) * DD + k0 + k4);
            float h0 = __uint_as_float(cvt_tf32(x.x));
            float h1 = __uint_as_float(cvt_tf32(x.y));
            float h2 = __uint_as_float(cvt_tf32(x.z));
            float h3 = __uint_as_float(cvt_tf32(x.w));
            *(float4*)(Ah + m * 68 + k4) = make_float4(h0, h1, h2, h3);
            *(float4*)(Al + m * 68 + k4) = make_float4(
                __uint_as_float(cvt_tf32(x.x - h0)), __uint_as_float(cvt_tf32(x.y - h1)),
                __uint_as_float(cvt_tf32(x.z - h2)), __uint_as_float(cvt_tf32(x.w - h3)));
        }
        for (int i = t; i < 1024; i += 256) {
            int k = i >> 4, n4 = (i & 15) * 4;
            float4 x = *(const float4*)(Wo + (k0 + k) * DD + colBase + n4);
            float h0 = __uint_as_float(cvt_tf32(x.x));
            float h1 = __uint_as_float(cvt_tf32(x.y));
            float h2 = __uint_as_float(cvt_tf32(x.z));
            float h3 = __uint_as_float(cvt_tf32(x.w));
            *(float4*)(Bh + k * 68 + n4) = make_float4(h0, h1, h2, h3);
            *(float4*)(Bl + k * 68 + n4) = make_float4(
                __uint_as_float(cvt_tf32(x.x - h0)), __uint_as_float(cvt_tf32(x.y - h1)),
                __uint_as_float(cvt_tf32(x.z - h2)), __uint_as_float(cvt_tf32(x.w - h3)));
        }
        __syncthreads();
#pragma unroll
        for (int ks = 0; ks < 8; ks++) {
            uint32 ah[4], al[4];
            {
                int off = (wm * 16 + lq) * 68 + ks * 8 + lc;
                ah[0] = __float_as_uint(Ah[off]);
                ah[1] = __float_as_uint(Ah[off + 8 * 68]);
                ah[2] = __float_as_uint(Ah[off + 4]);
                ah[3] = __float_as_uint(Ah[off + 8 * 68 + 4]);
                al[0] = __float_as_uint(Al[off]);
                al[1] = __float_as_uint(Al[off + 8 * 68]);
                al[2] = __float_as_uint(Al[off + 4]);
                al[3] = __float_as_uint(Al[off + 8 * 68 + 4]);
            }
#pragma unroll
            for (int nt = 0; nt < 2; nt++) {
                int off = (ks * 8 + lc) * 68 + wn * 16 + nt * 8 + lq;
                uint32 bh0 = __float_as_uint(Bh[off]);
                uint32 bh1 = __float_as_uint(Bh[off + 4 * 68]);
                uint32 bl0 = __float_as_uint(Bl[off]);
                uint32 bl1 = __float_as_uint(Bl[off + 4 * 68]);
                mma_tf32(cc[nt], ah, bh0, bh1);
                mma_tf32(cc[nt], al, bh0, bh1);
                mma_tf32(cc[nt], ah, bl0, bl1);
            }
        }
        __syncthreads();
    }

#pragma unroll
    for (int nt = 0; nt < 2; nt++) {
        int col0 = colBase + wn * 16 + nt * 8 + 2 * lc;
        float bx = bo[col0], by = bo[col0 + 1];
        int r0 = rowBase + wm * 16 + lq;
        *(float2*)(out + r0 * DD + col0) = make_float2(cc[nt][0] + bx, cc[nt][1] + by);
        *(float2*)(out + (r0 + 8) * DD + col0) = make_float2(cc[nt][2] + bx, cc[nt][3] + by);
    }
}

// ---------------- launch ----------------
extern "C" void kernel_launch(void* const* d_in, const int* in_sizes, int n_in,
                              void* d_out, int out_size) {
    const float* X         = (const float*)d_in[0];
    const void*  mask      = d_in[1];
    const int*   distances = (const int*)d_in[2];
    const float* Wq        = (const float*)d_in[3];
    const float* bq        = (const float*)d_in[4];
    const float* Wk        = (const float*)d_in[5];
    const float* bk        = (const float*)d_in[6];
    const float* Wv        = (const float*)d_in[7];
    const float* bv        = (const float*)d_in[8];
    const float* Wo        = (const float*)d_in[9];
    const float* bo        = (const float*)d_in[10];
    const float* rel_table = (const float*)d_in[11];
    const float* uvec      = (const float*)d_in[12];
    const float* vvec      = (const float*)d_in[13];

    float* out  = (float*)d_out;                       // (B,L,D)
    float* attn = (float*)d_out + BB * LL * DD;        // (B,H,L,L)

    const int gemm_smem = 17408 * 4;      // 69632 B
    const int attn_smem = 18400 * 4;      // 73600 B
    const int out_smem  = 13056 * 4;      // 52224 B
    static int smem_set = 0;
    if (!smem_set) {
        cudaFuncSetAttribute(fused_prep_qkv_kernel,
                             cudaFuncAttributeMaxDynamicSharedMemorySize, gemm_smem);
        cudaFuncSetAttribute(attn_kernel,
                             cudaFuncAttributeMaxDynamicSharedMemorySize, attn_smem);
        cudaFuncSetAttribute(out_gemm_kernel,
                             cudaFuncAttributeMaxDynamicSharedMemorySize, out_smem);
        smem_set = 1;
    }

    fused_prep_qkv_kernel<<<384 + 1024, 256, gemm_smem>>>(
        mask, distances, X, Wq, bq, Wk, bk, Wv, bv);
    attn_kernel<<<dim3(32, 32), 256, attn_smem>>>(uvec, vvec, rel_table, attn);
    out_gemm_kernel<<<dim3(4, 64), 256, out_smem>>>(Wo, bo, out);
}